// round 1
// baseline (speedup 1.0000x reference)
#include <cuda_runtime.h>

#define CONST __restrict__

static constexpr int B_  = 1024;
static constexpr int KO  = 10;
static constexpr int D_  = 32;
static constexpr int H_  = 512;
static constexpr int NN  = B_ * KO;     // 10240 nodes
static constexpr int EPN = KO - 1;      // 9 edges per source node
static constexpr int NE  = NN * EPN;    // 92160 edges
static constexpr float EPS = 1e-5f;

// ---- scratch (device globals; no allocations allowed) ----
__device__ float gP  [NN * H_];              // X@W1a + eb1
__device__ float gQ  [NN * H_];              // X@W1b
__device__ float gH2 [(size_t)NE * H_];      // edge hidden2 pre-LN (188 MB)
__device__ float gS  [NN * H_];              // grouped sum of LN(relu) rows
__device__ float gAGG[NN * H_];              // S@ew3 + 9*eb3
__device__ float gN1 [NN * H_];              // node hidden1 (post relu)
__device__ float gN2r[NN * H_];              // node hidden2 pre-LN
__device__ float gN2 [NN * H_];              // node hidden2 post LN+relu

// ---- generic fused GEMM: C[M, 512] = A @ B (+epilogue) ----
// MODE 0: gP   = states@ew1[0:32]  + eb1                (M=NN,  K=32)
// MODE 1: gQ   = states@ew1[32:64]                      (M=NN,  K=32)
// MODE 2: gH2  = relu(P[row]+Q[col]) @ ew2 + eb2        (M=NE,  K=512)
// MODE 3: gAGG = gS @ ew3 + 9*eb3                       (M=NN,  K=512)
// MODE 4: gN1  = relu([x|agg]@nw1' + nb1 + nw1[32+a])   (M=NN,  K=544)
// MODE 5: gN2r = gN1 @ nw2 + nb2                        (M=NN,  K=512)
static constexpr int BM = 128, BN = 128, BK = 16, TM = 8, TN = 8;

template <int MODE>
__global__ __launch_bounds__(256, 2)
void gemm_k(const float* CONST states, const float* CONST Bw,
            const float* CONST bias, const int* CONST act,
            const float* CONST nw1full)
{
    __shared__ float As[BK][BM];
    __shared__ float Bs[BK][BN];
    const int tid = threadIdx.x;
    const int tx = tid & 15, ty = tid >> 4;
    const int rowBase = blockIdx.y * BM;
    const int colBase = blockIdx.x * BN;

    constexpr int KT = (MODE == 0 || MODE == 1) ? 32 : (MODE == 4 ? 544 : 512);

    // each thread owns one A-tile row (8 consecutive k's)
    const int mm = tid >> 1;
    const int kb = (tid & 1) * 8;
    const int arow = rowBase + mm;

    const float *pA0 = nullptr, *pA1 = nullptr;
    if (MODE == 0 || MODE == 1) pA0 = states + (size_t)arow * D_;
    if (MODE == 2) {
        int node = arow / EPN;
        int jj = arow - node * EPN;
        int i = node % KO;
        int j = jj + (jj >= i ? 1 : 0);
        int cnode = node - i + j;
        pA0 = gP + (size_t)node * H_;
        pA1 = gQ + (size_t)cnode * H_;
    }
    if (MODE == 3) pA0 = gS + (size_t)arow * H_;
    if (MODE == 4) { pA0 = states + (size_t)arow * D_; pA1 = gAGG + (size_t)arow * H_; }
    if (MODE == 5) pA0 = gN1 + (size_t)arow * H_;

    float acc[TM][TN];
    #pragma unroll
    for (int i = 0; i < TM; i++)
        #pragma unroll
        for (int j = 0; j < TN; j++) acc[i][j] = 0.f;

    const int bk0 = tid >> 4;          // B-tile: one k-row per 16-thread group
    const int bn0 = (tid & 15) * 8;    // 8 consecutive columns (coalesced)

    for (int k0 = 0; k0 < KT; k0 += BK) {
        #pragma unroll
        for (int u = 0; u < 8; u++) {
            int k = k0 + kb + u;
            float v;
            if (MODE == 2)      v = fmaxf(pA0[k] + pA1[k], 0.f);
            else if (MODE == 4) v = (k < 32) ? pA0[k] : pA1[k - 32];
            else                v = pA0[k];
            As[kb + u][mm] = v;
        }
        {
            int k = k0 + bk0;
            const float* brow;
            if (MODE == 4) brow = Bw + (size_t)((k < 32) ? k : k + 4) * H_;
            else           brow = Bw + (size_t)k * H_;
            #pragma unroll
            for (int u = 0; u < 8; u++)
                Bs[bk0][bn0 + u] = brow[colBase + bn0 + u];
        }
        __syncthreads();
        #pragma unroll
        for (int kk = 0; kk < BK; kk++) {
            float a[TM], b[TN];
            #pragma unroll
            for (int i = 0; i < TM; i++) a[i] = As[kk][ty * TM + i];
            #pragma unroll
            for (int j = 0; j < TN; j++) b[j] = Bs[kk][tx * TN + j];
            #pragma unroll
            for (int i = 0; i < TM; i++)
                #pragma unroll
                for (int j = 0; j < TN; j++)
                    acc[i][j] = fmaf(a[i], b[j], acc[i][j]);
        }
        __syncthreads();
    }

    float* Cp;
    if      (MODE == 0) Cp = gP;
    else if (MODE == 1) Cp = gQ;
    else if (MODE == 2) Cp = gH2;
    else if (MODE == 3) Cp = gAGG;
    else if (MODE == 4) Cp = gN1;
    else                Cp = gN2r;

    #pragma unroll
    for (int i = 0; i < TM; i++) {
        int row = rowBase + ty * TM + i;
        #pragma unroll
        for (int j = 0; j < TN; j++) {
            int col = colBase + tx * TN + j;
            float v = acc[i][j];
            if (MODE == 0 || MODE == 2 || MODE == 5) v += bias[col];
            if (MODE == 3) v += 9.f * bias[col];
            if (MODE == 4) {
                v += bias[col] + nw1full[(size_t)(32 + act[row / KO]) * H_ + col];
                v = fmaxf(v, 0.f);
            }
            Cp[(size_t)row * H_ + col] = v;
        }
    }
}

// ---- per-node: LN + relu each of the 9 edge rows, sum into gS ----
__global__ __launch_bounds__(256)
void ln_sum_k(const float* CONST g, const float* CONST bt)
{
    const int n = blockIdx.x;
    const int t = threadIdx.x;
    __shared__ float red[256];
    const float g0 = g[t], g1 = g[t + 256];
    const float b0 = bt[t], b1 = bt[t + 256];
    float s0 = 0.f, s1 = 0.f;
    for (int e = 0; e < EPN; e++) {
        const float* rp = gH2 + (size_t)(n * EPN + e) * H_;
        float v0 = rp[t], v1 = rp[t + 256];
        red[t] = v0 + v1;
        __syncthreads();
        #pragma unroll
        for (int s = 128; s > 0; s >>= 1) { if (t < s) red[t] += red[t + s]; __syncthreads(); }
        float mean = red[0] * (1.f / 512.f);
        __syncthreads();
        float d0 = v0 - mean, d1 = v1 - mean;
        red[t] = d0 * d0 + d1 * d1;
        __syncthreads();
        #pragma unroll
        for (int s = 128; s > 0; s >>= 1) { if (t < s) red[t] += red[t + s]; __syncthreads(); }
        float rstd = rsqrtf(red[0] * (1.f / 512.f) + EPS);
        __syncthreads();
        s0 += fmaxf(d0 * rstd * g0 + b0, 0.f);
        s1 += fmaxf(d1 * rstd * g1 + b1, 0.f);
    }
    gS[(size_t)n * H_ + t]       = s0;
    gS[(size_t)n * H_ + t + 256] = s1;
}

// ---- per-node: LN + relu of gN2r -> gN2 ----
__global__ __launch_bounds__(256)
void ln2_k(const float* CONST g, const float* CONST bt)
{
    const int n = blockIdx.x;
    const int t = threadIdx.x;
    __shared__ float red[256];
    const float* rp = gN2r + (size_t)n * H_;
    float v0 = rp[t], v1 = rp[t + 256];
    red[t] = v0 + v1;
    __syncthreads();
    #pragma unroll
    for (int s = 128; s > 0; s >>= 1) { if (t < s) red[t] += red[t + s]; __syncthreads(); }
    float mean = red[0] * (1.f / 512.f);
    __syncthreads();
    float d0 = v0 - mean, d1 = v1 - mean;
    red[t] = d0 * d0 + d1 * d1;
    __syncthreads();
    #pragma unroll
    for (int s = 128; s > 0; s >>= 1) { if (t < s) red[t] += red[t + s]; __syncthreads(); }
    float rstd = rsqrtf(red[0] * (1.f / 512.f) + EPS);
    gN2[(size_t)n * H_ + t]       = fmaxf(d0 * rstd * g[t] + bt[t], 0.f);
    gN2[(size_t)n * H_ + t + 256] = fmaxf(d1 * rstd * g[t + 256] + bt[t + 256], 0.f);
}

// ---- out[10240, 32] = gN2 @ nw3 + nb3 ----
__global__ __launch_bounds__(256)
void n3_k(const float* CONST w3, const float* CONST b3, float* CONST out)
{
    __shared__ float xs[8][H_];
    const int r0 = blockIdx.x * 8;
    const int t = threadIdx.x;
    for (int i = t; i < 8 * H_; i += 256)
        xs[i >> 9][i & 511] = gN2[(size_t)(r0 + (i >> 9)) * H_ + (i & 511)];
    __syncthreads();
    const int lr = t >> 5, c = t & 31;
    float accv = b3[c];
    #pragma unroll 8
    for (int k = 0; k < H_; k++)
        accv = fmaf(xs[lr][k], w3[k * D_ + c], accv);
    out[(size_t)(r0 + lr) * D_ + c] = accv;
}

extern "C" void kernel_launch(void* const* d_in, const int* in_sizes, int n_in,
                              void* d_out, int out_size)
{
    (void)in_sizes; (void)n_in; (void)out_size;
    const float* states = (const float*)d_in[0];
    const int*   action = (const int*)  d_in[1];   // jnp.int64 downgraded to int32 (x64 off)
    const float* ew1 = (const float*)d_in[2];
    const float* eb1 = (const float*)d_in[3];
    const float* ew2 = (const float*)d_in[4];
    const float* eb2 = (const float*)d_in[5];
    const float* eg  = (const float*)d_in[6];
    const float* ebt = (const float*)d_in[7];
    const float* ew3 = (const float*)d_in[8];
    const float* eb3 = (const float*)d_in[9];
    const float* nw1 = (const float*)d_in[10];
    const float* nb1 = (const float*)d_in[11];
    const float* nw2 = (const float*)d_in[12];
    const float* nb2 = (const float*)d_in[13];
    const float* ng  = (const float*)d_in[14];
    const float* nbt = (const float*)d_in[15];
    const float* nw3 = (const float*)d_in[16];
    const float* nb3 = (const float*)d_in[17];
    float* out = (float*)d_out;

    dim3 blk(256);
    gemm_k<0><<<dim3(4, NN / BM), blk>>>(states, ew1,            eb1, nullptr, nullptr);
    gemm_k<1><<<dim3(4, NN / BM), blk>>>(states, ew1 + 32 * H_,  nullptr, nullptr, nullptr);
    gemm_k<2><<<dim3(4, NE / BM), blk>>>(nullptr, ew2,           eb2, nullptr, nullptr);
    ln_sum_k<<<NN, 256>>>(eg, ebt);
    gemm_k<3><<<dim3(4, NN / BM), blk>>>(nullptr, ew3,           eb3, nullptr, nullptr);
    gemm_k<4><<<dim3(4, NN / BM), blk>>>(states, nw1,            nb1, action,  nw1);
    gemm_k<5><<<dim3(4, NN / BM), blk>>>(nullptr, nw2,           nb2, nullptr, nullptr);
    ln2_k<<<NN, 256>>>(ng, nbt);
    n3_k<<<NN / 8, 256>>>(nw3, nb3, out);
}

// round 2
// speedup vs baseline: 1.9722x; 1.9722x over previous
#include <cuda_runtime.h>
#include <cuda_bf16.h>
#include <cstdint>

#define CONST __restrict__

static constexpr int B_  = 1024;
static constexpr int KO  = 10;
static constexpr int D_  = 32;
static constexpr int H_  = 512;
static constexpr int NN  = B_ * KO;     // 10240 nodes
static constexpr int EPN = KO - 1;      // 9 edges per source node
static constexpr int NE  = NN * EPN;    // 92160 edges
static constexpr float EPS = 1e-5f;

// ---- scratch (device globals; no allocations allowed) ----
__device__ float gP  [NN * H_];
__device__ float gQ  [NN * H_];
__device__ float gH2 [(size_t)NE * H_];      // 188 MB
__device__ float gS  [NN * H_];
__device__ float gAGG[NN * H_];
__device__ float gN1 [NN * H_];
__device__ float gN2r[NN * H_];
__device__ float gN2 [NN * H_];

// ===================== split-bf16 tensor-core GEMM =====================
// C[M,512] = A @ B (+ epilogue), A supplied per MODE (see round-1 algebra)
// MODE 0: gP   = states@ew1[0:32]  + eb1                (K=32)
// MODE 1: gQ   = states@ew1[32:64]                      (K=32)
// MODE 2: gH2  = relu(P[row]+Q[col]) @ ew2 + eb2        (K=512, M=NE)
// MODE 3: gAGG = gS @ ew3 + 9*eb3                       (K=512)
// MODE 4: gN1  = relu([x|agg]@nw1' + nb1 + nw1[32+a])   (K=544)
// MODE 5: gN2r = gN1 @ nw2 + nb2                        (K=512)

static constexpr int BM = 128, BN = 128, BK = 16, BKP = 18;

__device__ __forceinline__ void mma_bf16(float* c, uint32_t a0, uint32_t a1,
                                         uint32_t a2, uint32_t a3,
                                         uint32_t b0, uint32_t b1)
{
    asm volatile(
        "mma.sync.aligned.m16n8k16.row.col.f32.bf16.bf16.f32 "
        "{%0,%1,%2,%3}, {%4,%5,%6,%7}, {%8,%9}, {%0,%1,%2,%3};\n"
        : "+f"(c[0]), "+f"(c[1]), "+f"(c[2]), "+f"(c[3])
        : "r"(a0), "r"(a1), "r"(a2), "r"(a3), "r"(b0), "r"(b1));
}

__device__ __forceinline__ void split4(float4 v, __nv_bfloat16* hi, __nv_bfloat16* lo)
{
    float f[4] = {v.x, v.y, v.z, v.w};
    #pragma unroll
    for (int i = 0; i < 4; i++) {
        __nv_bfloat16 h = __float2bfloat16(f[i]);
        hi[i] = h;
        lo[i] = __float2bfloat16(f[i] - __bfloat162float(h));
    }
}

template <int MODE>
__global__ __launch_bounds__(256, 2)
void tgemm_k(const float* CONST states, const float* CONST Bw,
             const float* CONST bias, const int* CONST act,
             const float* CONST nw1full)
{
    __shared__ __align__(16) __nv_bfloat16 Ah[BM][BKP];
    __shared__ __align__(16) __nv_bfloat16 Al[BM][BKP];
    __shared__ __align__(16) __nv_bfloat16 Bh[BN][BKP];
    __shared__ __align__(16) __nv_bfloat16 Bl[BN][BKP];

    const int tid = threadIdx.x;
    const int rowBase = blockIdx.y * BM;
    const int colBase = blockIdx.x * BN;
    constexpr int KT = (MODE == 0 || MODE == 1) ? 32 : (MODE == 4 ? 544 : 512);

    // ---- A-source pointers for this thread's fill row ----
    const int fr = tid >> 1;              // 0..127 : A row within tile
    const int fks = (tid & 1) * 8;        // 0 or 8 : k offset
    const int arow = rowBase + fr;
    const float *pA0 = nullptr, *pA1 = nullptr;
    if (MODE == 0 || MODE == 1) pA0 = states + (size_t)arow * D_;
    if (MODE == 2) {
        int node = arow / EPN;
        int jj = arow - node * EPN;
        int i = node % KO;
        int j = jj + (jj >= i ? 1 : 0);
        int cnode = node - i + j;
        pA0 = gP + (size_t)node * H_;
        pA1 = gQ + (size_t)cnode * H_;
    }
    if (MODE == 3) pA0 = gS + (size_t)arow * H_;
    if (MODE == 4) { pA0 = states + (size_t)arow * D_; pA1 = gAGG + (size_t)arow * H_; }
    if (MODE == 5) pA0 = gN1 + (size_t)arow * H_;

    // ---- B fill mapping ----
    const int fkk = tid >> 4;             // 0..15 : k row within tile
    const int fn0 = (tid & 15) * 8;       // 8 consecutive cols

    // ---- warp/mma mapping ----
    const int warp = tid >> 5, lane = tid & 31;
    const int wm = warp >> 2, wn = warp & 3;        // 2x4 warp grid, tile 64x32
    const int g = lane >> 2, tg = lane & 3;

    float acc[4][4][4];
    #pragma unroll
    for (int a = 0; a < 4; a++)
        #pragma unroll
        for (int b = 0; b < 4; b++)
            #pragma unroll
            for (int c = 0; c < 4; c++) acc[a][b][c] = 0.f;

    for (int k0 = 0; k0 < KT; k0 += BK) {
        // ------- fill A (split) -------
        {
            float4 v0, v1;
            const int k = k0 + fks;
            if (MODE == 2) {
                float4 p0 = *(const float4*)(pA0 + k);
                float4 p1 = *(const float4*)(pA0 + k + 4);
                float4 q0 = *(const float4*)(pA1 + k);
                float4 q1 = *(const float4*)(pA1 + k + 4);
                v0 = make_float4(fmaxf(p0.x + q0.x, 0.f), fmaxf(p0.y + q0.y, 0.f),
                                 fmaxf(p0.z + q0.z, 0.f), fmaxf(p0.w + q0.w, 0.f));
                v1 = make_float4(fmaxf(p1.x + q1.x, 0.f), fmaxf(p1.y + q1.y, 0.f),
                                 fmaxf(p1.z + q1.z, 0.f), fmaxf(p1.w + q1.w, 0.f));
            } else if (MODE == 4) {
                const float* src = (k < 32) ? (pA0 + k) : (pA1 + k - 32);
                v0 = *(const float4*)(src);
                v1 = *(const float4*)(src + 4);
            } else {
                v0 = *(const float4*)(pA0 + k);
                v1 = *(const float4*)(pA0 + k + 4);
            }
            split4(v0, &Ah[fr][fks],     &Al[fr][fks]);
            split4(v1, &Ah[fr][fks + 4], &Al[fr][fks + 4]);
        }
        // ------- fill B (split, transposed to [n][k]) -------
        {
            const int k = k0 + fkk;
            const int krow = (MODE == 4) ? ((k < 32) ? k : k + 4) : k;
            const float* brow = Bw + (size_t)krow * H_ + colBase + fn0;
            float4 b0 = *(const float4*)(brow);
            float4 b1 = *(const float4*)(brow + 4);
            __nv_bfloat16 hh[8], ll[8];
            split4(b0, hh, ll);
            split4(b1, hh + 4, ll + 4);
            #pragma unroll
            for (int u = 0; u < 8; u++) {
                Bh[fn0 + u][fkk] = hh[u];
                Bl[fn0 + u][fkk] = ll[u];
            }
        }
        __syncthreads();

        // ------- mma -------
        uint32_t ahf[4][4], alf[4][4];
        #pragma unroll
        for (int mt = 0; mt < 4; mt++) {
            const int m0 = wm * 64 + mt * 16;
            ahf[mt][0] = *(const uint32_t*)&Ah[m0 + g][2 * tg];
            ahf[mt][1] = *(const uint32_t*)&Ah[m0 + g + 8][2 * tg];
            ahf[mt][2] = *(const uint32_t*)&Ah[m0 + g][2 * tg + 8];
            ahf[mt][3] = *(const uint32_t*)&Ah[m0 + g + 8][2 * tg + 8];
            alf[mt][0] = *(const uint32_t*)&Al[m0 + g][2 * tg];
            alf[mt][1] = *(const uint32_t*)&Al[m0 + g + 8][2 * tg];
            alf[mt][2] = *(const uint32_t*)&Al[m0 + g][2 * tg + 8];
            alf[mt][3] = *(const uint32_t*)&Al[m0 + g + 8][2 * tg + 8];
        }
        #pragma unroll
        for (int nt = 0; nt < 4; nt++) {
            const int nc = wn * 32 + nt * 8 + g;
            const uint32_t bh0 = *(const uint32_t*)&Bh[nc][2 * tg];
            const uint32_t bh1 = *(const uint32_t*)&Bh[nc][2 * tg + 8];
            const uint32_t bl0 = *(const uint32_t*)&Bl[nc][2 * tg];
            const uint32_t bl1 = *(const uint32_t*)&Bl[nc][2 * tg + 8];
            #pragma unroll
            for (int mt = 0; mt < 4; mt++) {
                mma_bf16(acc[mt][nt], ahf[mt][0], ahf[mt][1], ahf[mt][2], ahf[mt][3], bh0, bh1);
                mma_bf16(acc[mt][nt], ahf[mt][0], ahf[mt][1], ahf[mt][2], ahf[mt][3], bl0, bl1);
                mma_bf16(acc[mt][nt], alf[mt][0], alf[mt][1], alf[mt][2], alf[mt][3], bh0, bh1);
            }
        }
        __syncthreads();
    }

    // ------- epilogue + store -------
    float* Cp;
    if      (MODE == 0) Cp = gP;
    else if (MODE == 1) Cp = gQ;
    else if (MODE == 2) Cp = gH2;
    else if (MODE == 3) Cp = gAGG;
    else if (MODE == 4) Cp = gN1;
    else                Cp = gN2r;

    #pragma unroll
    for (int mt = 0; mt < 4; mt++) {
        const int row0 = rowBase + wm * 64 + mt * 16 + g;
        const int row1 = row0 + 8;
        #pragma unroll
        for (int nt = 0; nt < 4; nt++) {
            const int col = colBase + wn * 32 + nt * 8 + 2 * tg;
            float v0 = acc[mt][nt][0], v1 = acc[mt][nt][1];
            float v2 = acc[mt][nt][2], v3 = acc[mt][nt][3];
            if (MODE == 0 || MODE == 2 || MODE == 5) {
                float b0 = bias[col], b1 = bias[col + 1];
                v0 += b0; v1 += b1; v2 += b0; v3 += b1;
            }
            if (MODE == 3) {
                float b0 = 9.f * bias[col], b1 = 9.f * bias[col + 1];
                v0 += b0; v1 += b1; v2 += b0; v3 += b1;
            }
            if (MODE == 4) {
                float b0 = bias[col], b1 = bias[col + 1];
                const int a0r = act[row0 / KO], a1r = act[row1 / KO];
                v0 = fmaxf(v0 + b0 + nw1full[(size_t)(32 + a0r) * H_ + col], 0.f);
                v1 = fmaxf(v1 + b1 + nw1full[(size_t)(32 + a0r) * H_ + col + 1], 0.f);
                v2 = fmaxf(v2 + b0 + nw1full[(size_t)(32 + a1r) * H_ + col], 0.f);
                v3 = fmaxf(v3 + b1 + nw1full[(size_t)(32 + a1r) * H_ + col + 1], 0.f);
            }
            *(float2*)(Cp + (size_t)row0 * H_ + col) = make_float2(v0, v1);
            *(float2*)(Cp + (size_t)row1 * H_ + col) = make_float2(v2, v3);
        }
    }
}

// ===================== LN + relu + 9-row sum (warp-per-row) =====================
__global__ __launch_bounds__(256)
void ln_sum_k(const float* CONST g, const float* CONST bt)
{
    const int n = blockIdx.x;
    const int tid = threadIdx.x, warp = tid >> 5, lane = tid & 31;
    __shared__ float sAcc[H_], sG[H_], sBt[H_];
    for (int i = tid; i < H_; i += 256) { sAcc[i] = 0.f; sG[i] = g[i]; sBt[i] = bt[i]; }
    __syncthreads();

    for (int e = warp; e < EPN; e += 8) {
        const float4* rp = (const float4*)(gH2 + (size_t)(n * EPN + e) * H_);
        float4 v[4];
        float s = 0.f, sq = 0.f;
        #pragma unroll
        for (int j = 0; j < 4; j++) {
            v[j] = rp[lane + 32 * j];
            s  += v[j].x + v[j].y + v[j].z + v[j].w;
            sq += v[j].x * v[j].x + v[j].y * v[j].y + v[j].z * v[j].z + v[j].w * v[j].w;
        }
        #pragma unroll
        for (int o = 16; o > 0; o >>= 1) {
            s  += __shfl_xor_sync(0xffffffff, s, o);
            sq += __shfl_xor_sync(0xffffffff, sq, o);
        }
        const float mean = s * (1.f / 512.f);
        const float var = sq * (1.f / 512.f) - mean * mean;
        const float rstd = rsqrtf(var + EPS);
        #pragma unroll
        for (int j = 0; j < 4; j++) {
            const int c = (lane + 32 * j) * 4;
            float f[4] = {v[j].x, v[j].y, v[j].z, v[j].w};
            #pragma unroll
            for (int u = 0; u < 4; u++) {
                float y = fmaxf((f[u] - mean) * rstd * sG[c + u] + sBt[c + u], 0.f);
                atomicAdd(&sAcc[c + u], y);
            }
        }
    }
    __syncthreads();
    for (int i = tid; i < H_; i += 256) gS[(size_t)n * H_ + i] = sAcc[i];
}

// ===================== LN + relu of gN2r (warp-per-node) =====================
__global__ __launch_bounds__(256)
void ln2_k(const float* CONST g, const float* CONST bt)
{
    const int tid = threadIdx.x, warp = tid >> 5, lane = tid & 31;
    const int n = blockIdx.x * 8 + warp;
    const float4* rp = (const float4*)(gN2r + (size_t)n * H_);
    float4 v[4];
    float s = 0.f, sq = 0.f;
    #pragma unroll
    for (int j = 0; j < 4; j++) {
        v[j] = rp[lane + 32 * j];
        s  += v[j].x + v[j].y + v[j].z + v[j].w;
        sq += v[j].x * v[j].x + v[j].y * v[j].y + v[j].z * v[j].z + v[j].w * v[j].w;
    }
    #pragma unroll
    for (int o = 16; o > 0; o >>= 1) {
        s  += __shfl_xor_sync(0xffffffff, s, o);
        sq += __shfl_xor_sync(0xffffffff, sq, o);
    }
    const float mean = s * (1.f / 512.f);
    const float var = sq * (1.f / 512.f) - mean * mean;
    const float rstd = rsqrtf(var + EPS);
    float4* op = (float4*)(gN2 + (size_t)n * H_);
    #pragma unroll
    for (int j = 0; j < 4; j++) {
        const int c = (lane + 32 * j) * 4;
        float4 o4;
        o4.x = fmaxf((v[j].x - mean) * rstd * g[c]     + bt[c],     0.f);
        o4.y = fmaxf((v[j].y - mean) * rstd * g[c + 1] + bt[c + 1], 0.f);
        o4.z = fmaxf((v[j].z - mean) * rstd * g[c + 2] + bt[c + 2], 0.f);
        o4.w = fmaxf((v[j].w - mean) * rstd * g[c + 3] + bt[c + 3], 0.f);
        op[lane + 32 * j] = o4;
    }
}

// ===================== out = gN2 @ nw3 + nb3 =====================
__global__ __launch_bounds__(256)
void n3_k(const float* CONST w3, const float* CONST b3, float* CONST out)
{
    __shared__ float xs[8][H_];
    const int r0 = blockIdx.x * 8;
    const int t = threadIdx.x;
    for (int i = t; i < 8 * H_; i += 256)
        xs[i >> 9][i & 511] = gN2[(size_t)(r0 + (i >> 9)) * H_ + (i & 511)];
    __syncthreads();
    const int lr = t >> 5, c = t & 31;
    float accv = b3[c];
    #pragma unroll 8
    for (int k = 0; k < H_; k++)
        accv = fmaf(xs[lr][k], w3[k * D_ + c], accv);
    out[(size_t)(r0 + lr) * D_ + c] = accv;
}

extern "C" void kernel_launch(void* const* d_in, const int* in_sizes, int n_in,
                              void* d_out, int out_size)
{
    (void)in_sizes; (void)n_in; (void)out_size;
    const float* states = (const float*)d_in[0];
    const int*   action = (const int*)  d_in[1];
    const float* ew1 = (const float*)d_in[2];
    const float* eb1 = (const float*)d_in[3];
    const float* ew2 = (const float*)d_in[4];
    const float* eb2 = (const float*)d_in[5];
    const float* eg  = (const float*)d_in[6];
    const float* ebt = (const float*)d_in[7];
    const float* ew3 = (const float*)d_in[8];
    const float* eb3 = (const float*)d_in[9];
    const float* nw1 = (const float*)d_in[10];
    const float* nb1 = (const float*)d_in[11];
    const float* nw2 = (const float*)d_in[12];
    const float* nb2 = (const float*)d_in[13];
    const float* ng  = (const float*)d_in[14];
    const float* nbt = (const float*)d_in[15];
    const float* nw3 = (const float*)d_in[16];
    const float* nb3 = (const float*)d_in[17];
    float* out = (float*)d_out;

    dim3 blk(256);
    tgemm_k<0><<<dim3(4, NN / BM), blk>>>(states, ew1,           eb1, nullptr, nullptr);
    tgemm_k<1><<<dim3(4, NN / BM), blk>>>(states, ew1 + 32 * H_, nullptr, nullptr, nullptr);
    tgemm_k<2><<<dim3(4, NE / BM), blk>>>(nullptr, ew2,          eb2, nullptr, nullptr);
    ln_sum_k<<<NN, 256>>>(eg, ebt);
    tgemm_k<3><<<dim3(4, NN / BM), blk>>>(nullptr, ew3,          eb3, nullptr, nullptr);
    tgemm_k<4><<<dim3(4, NN / BM), blk>>>(states, nw1,           nb1, action,  nw1);
    tgemm_k<5><<<dim3(4, NN / BM), blk>>>(nullptr, nw2,          nb2, nullptr, nullptr);
    ln2_k<<<NN / 8, 256>>>(ng, nbt);
    n3_k<<<NN / 8, 256>>>(nw3, nb3, out);
}

// round 4
// speedup vs baseline: 2.1567x; 1.0936x over previous
#include <cuda_runtime.h>
#include <cuda_bf16.h>
#include <cstdint>

#define CONST __restrict__

static constexpr int B_  = 1024;
static constexpr int KO  = 10;
static constexpr int D_  = 32;
static constexpr int H_  = 512;
static constexpr int NN  = B_ * KO;     // 10240 nodes
static constexpr int EPN = KO - 1;      // 9 edges per node
static constexpr int NE  = NN * EPN;    // 92160 edges
static constexpr float EPS = 1e-5f;

static constexpr int NSLICE = 4;
static constexpr int EDGES_PER_SLICE = NE / NSLICE;   // 23040
static constexpr int NODES_PER_SLICE = NN / NSLICE;   // 2560

// ---------------- scratch ----------------
__device__ float gP  [NN * H_];
__device__ float gQ  [NN * H_];
__device__ float gH2 [(size_t)NE * H_];
__device__ float gS  [NN * H_];
__device__ float gAGG[NN * H_];
__device__ float gN1 [NN * H_];
__device__ float gN2r[NN * H_];
__device__ float gN2 [NN * H_];

// pre-split transposed weights [N][K], hi/lo planes, 16B aligned for uint4 loads
__device__ __align__(16) __nv_bfloat16 gW0h[H_ * 32],  gW0l[H_ * 32];
__device__ __align__(16) __nv_bfloat16 gW1h[H_ * 32],  gW1l[H_ * 32];
__device__ __align__(16) __nv_bfloat16 gW2h[H_ * H_],  gW2l[H_ * H_];
__device__ __align__(16) __nv_bfloat16 gW3h[H_ * H_],  gW3l[H_ * H_];
__device__ __align__(16) __nv_bfloat16 gW4h[H_ * 544], gW4l[H_ * 544];
__device__ __align__(16) __nv_bfloat16 gW5h[H_ * H_],  gW5l[H_ * H_];

__device__ __forceinline__ void mma_bf16(float* c, uint32_t a0, uint32_t a1,
                                         uint32_t a2, uint32_t a3,
                                         uint32_t b0, uint32_t b1)
{
    asm volatile(
        "mma.sync.aligned.m16n8k16.row.col.f32.bf16.bf16.f32 "
        "{%0,%1,%2,%3}, {%4,%5,%6,%7}, {%8,%9}, {%0,%1,%2,%3};\n"
        : "+f"(c[0]), "+f"(c[1]), "+f"(c[2]), "+f"(c[3])
        : "r"(a0), "r"(a1), "r"(a2), "r"(a3), "r"(b0), "r"(b1));
}

// ---------------- weight prep: split + transpose ----------------
__global__ void prep_T(const float* CONST src, __nv_bfloat16* CONST dh,
                       __nv_bfloat16* CONST dl, int K, int N, int skip32)
{
    int idx = blockIdx.x * 256 + threadIdx.x;
    if (idx >= K * N) return;
    int k = idx % K, n = idx / K;
    int sr = (skip32 && k >= 32) ? k + 4 : k;
    float v = src[(size_t)sr * N + n];
    __nv_bfloat16 h = __float2bfloat16(v);
    dh[idx] = h;
    dl[idx] = __float2bfloat16(v - __bfloat162float(h));
}

// ---------------- pipelined split-bf16 mma.sync GEMM ----------------
// MODE 0: gP   = states@ew1a + eb1              (K=32)
// MODE 1: gQ   = states@ew1b                    (K=32)
// MODE 2: gH2  = relu(P[n]+Q[c]) @ ew2 + eb2    (K=512, M=NE, sliced)
// MODE 3: gAGG = gS @ ew3 + 9*eb3               (K=512)
// MODE 4: gN1  = relu([x|agg]@nw1' + nb1 + row) (K=544)
// MODE 5: gN2r = gN1 @ nw2 + nb2                (K=512)
static constexpr int BKC = 32;          // k chunk
static constexpr int LDP = 40;          // padded row (elems): 80B = 20 banks, conflict-free

template <int MODE>
__global__ __launch_bounds__(256)
void tg(const float* CONST states, const __nv_bfloat16* CONST Wh,
        const __nv_bfloat16* CONST Wl, const float* CONST bias,
        const int* CONST act, const float* CONST nw1full, int rowOff)
{
    __shared__ __align__(16) __nv_bfloat16 sAh[128 * LDP];
    __shared__ __align__(16) __nv_bfloat16 sAl[128 * LDP];
    __shared__ __align__(16) __nv_bfloat16 sBh[128 * LDP];
    __shared__ __align__(16) __nv_bfloat16 sBl[128 * LDP];

    constexpr int KT = (MODE <= 1) ? 32 : (MODE == 4 ? 544 : 512);
    constexpr int NC = KT / BKC;

    const int tid = threadIdx.x, warp = tid >> 5, lane = tid & 31;
    const int rowBase = rowOff + blockIdx.y * 128;
    const int colBase = blockIdx.x * 128;

    // fill mapping: row fr, k-half fks
    const int fr  = tid >> 1;
    const int fks = (tid & 1) * 16;
    const int arow = rowBase + fr;

    const float* pA = nullptr;
    const float* pP = nullptr;
    const float* pQ = nullptr;
    const float* pAgg = nullptr;
    if constexpr (MODE == 0 || MODE == 1) pA = states + (size_t)arow * D_;
    if constexpr (MODE == 2) {
        int node = arow / EPN;
        int jj = arow - node * EPN;
        int i = node % KO;
        int j = jj + (jj >= i ? 1 : 0);
        int cn = node - i + j;
        pP = gP + (size_t)node * H_;
        pQ = gQ + (size_t)cn * H_;
    }
    if constexpr (MODE == 3) pA = gS + (size_t)arow * H_;
    if constexpr (MODE == 4) { pA = states + (size_t)arow * D_; pAgg = gAGG + (size_t)arow * H_; }
    if constexpr (MODE == 5) pA = gN1 + (size_t)arow * H_;

    const __nv_bfloat16* bhRow = Wh + (size_t)(colBase + fr) * KT;
    const __nv_bfloat16* blRow = Wl + (size_t)(colBase + fr) * KT;

    // warp tiling: 2x4 warps, warp tile 64x32
    const int wm = warp >> 2, wn = warp & 3;
    const int g = lane >> 2, tg2 = (lane & 3) * 2;

    float acc[4][4][4];
    #pragma unroll
    for (int a = 0; a < 4; a++)
        #pragma unroll
        for (int b = 0; b < 4; b++)
            #pragma unroll
            for (int c = 0; c < 4; c++) acc[a][b][c] = 0.f;

    float fa[16];
    uint4 rbh[2], rbl[2];

    auto load_chunk = [&](int k0) {
        const int kk = k0 + fks;
        if constexpr (MODE == 2) {
            #pragma unroll
            for (int u = 0; u < 16; u += 4) {
                float4 p = *(const float4*)(pP + kk + u);
                float4 q = *(const float4*)(pQ + kk + u);
                fa[u]     = fmaxf(p.x + q.x, 0.f);
                fa[u + 1] = fmaxf(p.y + q.y, 0.f);
                fa[u + 2] = fmaxf(p.z + q.z, 0.f);
                fa[u + 3] = fmaxf(p.w + q.w, 0.f);
            }
        } else if constexpr (MODE == 4) {
            const float* s = (k0 == 0) ? (pA + fks) : (pAgg + kk - 32);
            #pragma unroll
            for (int u = 0; u < 16; u += 4) {
                float4 v = *(const float4*)(s + u);
                fa[u] = v.x; fa[u + 1] = v.y; fa[u + 2] = v.z; fa[u + 3] = v.w;
            }
        } else {
            #pragma unroll
            for (int u = 0; u < 16; u += 4) {
                float4 v = *(const float4*)(pA + kk + u);
                fa[u] = v.x; fa[u + 1] = v.y; fa[u + 2] = v.z; fa[u + 3] = v.w;
            }
        }
        rbh[0] = *(const uint4*)(bhRow + kk);
        rbh[1] = *(const uint4*)(bhRow + kk + 8);
        rbl[0] = *(const uint4*)(blRow + kk);
        rbl[1] = *(const uint4*)(blRow + kk + 8);
    };

    auto store_chunk = [&]() {
        __nv_bfloat16 h[16], l[16];
        #pragma unroll
        for (int u = 0; u < 16; u++) {
            h[u] = __float2bfloat16(fa[u]);
            l[u] = __float2bfloat16(fa[u] - __bfloat162float(h[u]));
        }
        const int base = fr * LDP + fks;
        *(uint4*)&sAh[base]     = *(const uint4*)&h[0];
        *(uint4*)&sAh[base + 8] = *(const uint4*)&h[8];
        *(uint4*)&sAl[base]     = *(const uint4*)&l[0];
        *(uint4*)&sAl[base + 8] = *(const uint4*)&l[8];
        *(uint4*)&sBh[base]     = rbh[0];
        *(uint4*)&sBh[base + 8] = rbh[1];
        *(uint4*)&sBl[base]     = rbl[0];
        *(uint4*)&sBl[base + 8] = rbl[1];
    };

    load_chunk(0);
    for (int c = 0; c < NC; c++) {
        store_chunk();
        __syncthreads();
        if (c + 1 < NC) load_chunk((c + 1) * BKC);

        #pragma unroll
        for (int kf = 0; kf < 2; kf++) {
            const int kb = kf * 16;
            uint32_t ah[4][4], al[4][4];
            #pragma unroll
            for (int mt = 0; mt < 4; mt++) {
                const int m0 = wm * 64 + mt * 16;
                const int r0 = (m0 + g) * LDP + kb + tg2;
                const int r1 = (m0 + g + 8) * LDP + kb + tg2;
                ah[mt][0] = *(const uint32_t*)&sAh[r0];
                ah[mt][1] = *(const uint32_t*)&sAh[r1];
                ah[mt][2] = *(const uint32_t*)&sAh[r0 + 8];
                ah[mt][3] = *(const uint32_t*)&sAh[r1 + 8];
                al[mt][0] = *(const uint32_t*)&sAl[r0];
                al[mt][1] = *(const uint32_t*)&sAl[r1];
                al[mt][2] = *(const uint32_t*)&sAl[r0 + 8];
                al[mt][3] = *(const uint32_t*)&sAl[r1 + 8];
            }
            #pragma unroll
            for (int nt = 0; nt < 4; nt++) {
                const int nc = (wn * 32 + nt * 8 + g) * LDP + kb + tg2;
                const uint32_t bh0 = *(const uint32_t*)&sBh[nc];
                const uint32_t bh1 = *(const uint32_t*)&sBh[nc + 8];
                const uint32_t bl0 = *(const uint32_t*)&sBl[nc];
                const uint32_t bl1 = *(const uint32_t*)&sBl[nc + 8];
                #pragma unroll
                for (int mt = 0; mt < 4; mt++) {
                    mma_bf16(acc[mt][nt], ah[mt][0], ah[mt][1], ah[mt][2], ah[mt][3], bh0, bh1);
                    mma_bf16(acc[mt][nt], ah[mt][0], ah[mt][1], ah[mt][2], ah[mt][3], bl0, bl1);
                    mma_bf16(acc[mt][nt], al[mt][0], al[mt][1], al[mt][2], al[mt][3], bh0, bh1);
                }
            }
        }
        __syncthreads();
    }

    // ------- epilogue -------
    float* Cp;
    if      constexpr (MODE == 0) Cp = gP;
    else if constexpr (MODE == 1) Cp = gQ;
    else if constexpr (MODE == 2) Cp = gH2;
    else if constexpr (MODE == 3) Cp = gAGG;
    else if constexpr (MODE == 4) Cp = gN1;
    else                          Cp = gN2r;

    #pragma unroll
    for (int mt = 0; mt < 4; mt++) {
        const int row0 = rowBase + wm * 64 + mt * 16 + g;
        const int row1 = row0 + 8;
        #pragma unroll
        for (int nt = 0; nt < 4; nt++) {
            const int col = colBase + wn * 32 + nt * 8 + tg2;
            float v0 = acc[mt][nt][0], v1 = acc[mt][nt][1];
            float v2 = acc[mt][nt][2], v3 = acc[mt][nt][3];
            if constexpr (MODE == 0 || MODE == 2 || MODE == 5) {
                float b0 = bias[col], b1 = bias[col + 1];
                v0 += b0; v1 += b1; v2 += b0; v3 += b1;
            }
            if constexpr (MODE == 3) {
                float b0 = 9.f * bias[col], b1 = 9.f * bias[col + 1];
                v0 += b0; v1 += b1; v2 += b0; v3 += b1;
            }
            if constexpr (MODE == 4) {
                float b0 = bias[col], b1 = bias[col + 1];
                const int a0r = act[row0 / KO], a1r = act[row1 / KO];
                v0 = fmaxf(v0 + b0 + nw1full[(size_t)(32 + a0r) * H_ + col], 0.f);
                v1 = fmaxf(v1 + b1 + nw1full[(size_t)(32 + a0r) * H_ + col + 1], 0.f);
                v2 = fmaxf(v2 + b0 + nw1full[(size_t)(32 + a1r) * H_ + col], 0.f);
                v3 = fmaxf(v3 + b1 + nw1full[(size_t)(32 + a1r) * H_ + col + 1], 0.f);
            }
            *(float2*)(Cp + (size_t)row0 * H_ + col) = make_float2(v0, v1);
            *(float2*)(Cp + (size_t)row1 * H_ + col) = make_float2(v2, v3);
        }
    }
}

// ---------------- LN + relu + 9-row sum (warp per node, register accum) ----------------
__global__ __launch_bounds__(256)
void ln_sum_k(const float* CONST g, const float* CONST bt, int nodeOff)
{
    const int tid = threadIdx.x, warp = tid >> 5, lane = tid & 31;
    const int n = nodeOff + blockIdx.x * 8 + warp;
    const float4* gg = (const float4*)g;
    const float4* bb = (const float4*)bt;
    float4 G[4], Bt[4], acc[4];
    #pragma unroll
    for (int j = 0; j < 4; j++) {
        G[j] = gg[lane + 32 * j];
        Bt[j] = bb[lane + 32 * j];
        acc[j] = make_float4(0.f, 0.f, 0.f, 0.f);
    }
    for (int e = 0; e < EPN; e++) {
        const float4* rp = (const float4*)(gH2 + (size_t)(n * EPN + e) * H_);
        float4 v[4];
        float s = 0.f, sq = 0.f;
        #pragma unroll
        for (int j = 0; j < 4; j++) {
            v[j] = rp[lane + 32 * j];
            s  += v[j].x + v[j].y + v[j].z + v[j].w;
            sq += v[j].x * v[j].x + v[j].y * v[j].y + v[j].z * v[j].z + v[j].w * v[j].w;
        }
        #pragma unroll
        for (int o = 16; o > 0; o >>= 1) {
            s  += __shfl_xor_sync(0xffffffff, s, o);
            sq += __shfl_xor_sync(0xffffffff, sq, o);
        }
        const float mean = s * (1.f / 512.f);
        const float rstd = rsqrtf(sq * (1.f / 512.f) - mean * mean + EPS);
        #pragma unroll
        for (int j = 0; j < 4; j++) {
            acc[j].x += fmaxf((v[j].x - mean) * rstd * G[j].x + Bt[j].x, 0.f);
            acc[j].y += fmaxf((v[j].y - mean) * rstd * G[j].y + Bt[j].y, 0.f);
            acc[j].z += fmaxf((v[j].z - mean) * rstd * G[j].z + Bt[j].z, 0.f);
            acc[j].w += fmaxf((v[j].w - mean) * rstd * G[j].w + Bt[j].w, 0.f);
        }
    }
    float4* op = (float4*)(gS + (size_t)n * H_);
    #pragma unroll
    for (int j = 0; j < 4; j++) op[lane + 32 * j] = acc[j];
}

// ---------------- LN + relu of gN2r ----------------
__global__ __launch_bounds__(256)
void ln2_k(const float* CONST g, const float* CONST bt)
{
    const int tid = threadIdx.x, warp = tid >> 5, lane = tid & 31;
    const int n = blockIdx.x * 8 + warp;
    const float4* rp = (const float4*)(gN2r + (size_t)n * H_);
    float4 v[4];
    float s = 0.f, sq = 0.f;
    #pragma unroll
    for (int j = 0; j < 4; j++) {
        v[j] = rp[lane + 32 * j];
        s  += v[j].x + v[j].y + v[j].z + v[j].w;
        sq += v[j].x * v[j].x + v[j].y * v[j].y + v[j].z * v[j].z + v[j].w * v[j].w;
    }
    #pragma unroll
    for (int o = 16; o > 0; o >>= 1) {
        s  += __shfl_xor_sync(0xffffffff, s, o);
        sq += __shfl_xor_sync(0xffffffff, sq, o);
    }
    const float mean = s * (1.f / 512.f);
    const float rstd = rsqrtf(sq * (1.f / 512.f) - mean * mean + EPS);
    float4* op = (float4*)(gN2 + (size_t)n * H_);
    #pragma unroll
    for (int j = 0; j < 4; j++) {
        const int c = (lane + 32 * j) * 4;
        float4 o4;
        o4.x = fmaxf((v[j].x - mean) * rstd * g[c]     + bt[c],     0.f);
        o4.y = fmaxf((v[j].y - mean) * rstd * g[c + 1] + bt[c + 1], 0.f);
        o4.z = fmaxf((v[j].z - mean) * rstd * g[c + 2] + bt[c + 2], 0.f);
        o4.w = fmaxf((v[j].w - mean) * rstd * g[c + 3] + bt[c + 3], 0.f);
        op[lane + 32 * j] = o4;
    }
}

// ---------------- out = gN2 @ nw3 + nb3 ----------------
__global__ __launch_bounds__(256)
void n3_k(const float* CONST w3, const float* CONST b3, float* CONST out)
{
    __shared__ float xs[8][H_];
    const int r0 = blockIdx.x * 8;
    const int t = threadIdx.x;
    for (int i = t; i < 8 * H_; i += 256)
        xs[i >> 9][i & 511] = gN2[(size_t)(r0 + (i >> 9)) * H_ + (i & 511)];
    __syncthreads();
    const int lr = t >> 5, c = t & 31;
    float accv = b3[c];
    #pragma unroll 8
    for (int k = 0; k < H_; k++)
        accv = fmaf(xs[lr][k], w3[k * D_ + c], accv);
    out[(size_t)(r0 + lr) * D_ + c] = accv;
}

// ---------------- launch ----------------
extern "C" void kernel_launch(void* const* d_in, const int* in_sizes, int n_in,
                              void* d_out, int out_size)
{
    (void)in_sizes; (void)n_in; (void)out_size;
    const float* states = (const float*)d_in[0];
    const int*   action = (const int*)  d_in[1];
    const float* ew1 = (const float*)d_in[2];
    const float* eb1 = (const float*)d_in[3];
    const float* ew2 = (const float*)d_in[4];
    const float* eb2 = (const float*)d_in[5];
    const float* eg  = (const float*)d_in[6];
    const float* ebt = (const float*)d_in[7];
    const float* ew3 = (const float*)d_in[8];
    const float* eb3 = (const float*)d_in[9];
    const float* nw1 = (const float*)d_in[10];
    const float* nb1 = (const float*)d_in[11];
    const float* nw2 = (const float*)d_in[12];
    const float* nb2 = (const float*)d_in[13];
    const float* ng  = (const float*)d_in[14];
    const float* nbt = (const float*)d_in[15];
    const float* nw3 = (const float*)d_in[16];
    const float* nb3 = (const float*)d_in[17];
    float* out = (float*)d_out;

    __nv_bfloat16 *w0h, *w0l, *w1h, *w1l, *w2h, *w2l, *w3h, *w3l, *w4h, *w4l, *w5h, *w5l;
    cudaGetSymbolAddress((void**)&w0h, gW0h); cudaGetSymbolAddress((void**)&w0l, gW0l);
    cudaGetSymbolAddress((void**)&w1h, gW1h); cudaGetSymbolAddress((void**)&w1l, gW1l);
    cudaGetSymbolAddress((void**)&w2h, gW2h); cudaGetSymbolAddress((void**)&w2l, gW2l);
    cudaGetSymbolAddress((void**)&w3h, gW3h); cudaGetSymbolAddress((void**)&w3l, gW3l);
    cudaGetSymbolAddress((void**)&w4h, gW4h); cudaGetSymbolAddress((void**)&w4l, gW4l);
    cudaGetSymbolAddress((void**)&w5h, gW5h); cudaGetSymbolAddress((void**)&w5l, gW5l);

    auto gsz = [](int e) { return (e + 255) / 256; };
    prep_T<<<gsz(H_ * 32),  256>>>(ew1,           w0h, w0l, 32,  H_, 0);
    prep_T<<<gsz(H_ * 32),  256>>>(ew1 + 32 * H_, w1h, w1l, 32,  H_, 0);
    prep_T<<<gsz(H_ * H_),  256>>>(ew2,           w2h, w2l, H_,  H_, 0);
    prep_T<<<gsz(H_ * H_),  256>>>(ew3,           w3h, w3l, H_,  H_, 0);
    prep_T<<<gsz(H_ * 544), 256>>>(nw1,           w4h, w4l, 544, H_, 1);
    prep_T<<<gsz(H_ * H_),  256>>>(nw2,           w5h, w5l, H_,  H_, 0);

    dim3 blk(256);
    tg<0><<<dim3(4, NN / 128), blk>>>(states, w0h, w0l, eb1, nullptr, nullptr, 0);
    tg<1><<<dim3(4, NN / 128), blk>>>(states, w1h, w1l, nullptr, nullptr, nullptr, 0);

    // edge GEMM + LN/sum, interleaved in L2-sized slices
    for (int s = 0; s < NSLICE; s++) {
        tg<2><<<dim3(4, EDGES_PER_SLICE / 128), blk>>>(nullptr, w2h, w2l, eb2,
                                                       nullptr, nullptr,
                                                       s * EDGES_PER_SLICE);
        ln_sum_k<<<NODES_PER_SLICE / 8, 256>>>(eg, ebt, s * NODES_PER_SLICE);
    }

    tg<3><<<dim3(4, NN / 128), blk>>>(nullptr, w3h, w3l, eb3, nullptr, nullptr, 0);
    tg<4><<<dim3(4, NN / 128), blk>>>(states, w4h, w4l, nb1, action, nw1, 0);
    tg<5><<<dim3(4, NN / 128), blk>>>(nullptr, w5h, w5l, nb2, nullptr, nullptr, 0);
    ln2_k<<<NN / 8, 256>>>(ng, nbt);
    n3_k<<<NN / 8, 256>>>(nw3, nb3, out);
}

// round 5
// speedup vs baseline: 2.7600x; 1.2797x over previous
#include <cuda_runtime.h>
#include <cuda_bf16.h>
#include <cstdint>

#define CONST __restrict__
using bf16 = __nv_bfloat16;

static constexpr int B_  = 1024;
static constexpr int KO  = 10;
static constexpr int D_  = 32;
static constexpr int H_  = 512;
static constexpr int NN  = B_ * KO;     // 10240
static constexpr int EPN = KO - 1;      // 9
static constexpr int NE  = NN * EPN;    // 92160
static constexpr float EPS = 1e-5f;
static constexpr int K4  = 544;         // node MLP layer-1 K

static constexpr int NSLICE = 4;
static constexpr int ESL = NE / NSLICE;   // 23040 edges/slice
static constexpr int NSL = NN / NSLICE;   // 2560 nodes/slice

// ---------------- scratch planes ----------------
__device__ __align__(16) bf16 gSTh[NN * D_],  gSTl[NN * D_];
__device__ __align__(16) bf16 gPh [NN * H_],  gPl [NN * H_];
__device__ __align__(16) bf16 gQh [NN * H_],  gQl [NN * H_];
__device__ __align__(16) bf16 gEh [(size_t)NE * H_], gEl[(size_t)NE * H_];
__device__ float gH2 [(size_t)NE * H_];
__device__ __align__(16) bf16 gSh [NN * H_],  gSl [NN * H_];
__device__ __align__(16) bf16 gA4h[NN * K4],  gA4l[NN * K4];
__device__ __align__(16) bf16 gN1h[NN * H_],  gN1l[NN * H_];
__device__ float gN2r[NN * H_], gN2[NN * H_];

// split transposed weights [N][K]
__device__ __align__(16) bf16 gW0h[H_ * 32],  gW0l[H_ * 32];
__device__ __align__(16) bf16 gW1h[H_ * 32],  gW1l[H_ * 32];
__device__ __align__(16) bf16 gW2h[H_ * H_],  gW2l[H_ * H_];
__device__ __align__(16) bf16 gW3h[H_ * H_],  gW3l[H_ * H_];
__device__ __align__(16) bf16 gW4h[H_ * K4],  gW4l[H_ * K4];
__device__ __align__(16) bf16 gW5h[H_ * H_],  gW5l[H_ * H_];

// ---------------- helpers ----------------
__device__ __forceinline__ uint32_t s2u(const void* p) {
    uint32_t a;
    asm("{ .reg .u64 t; cvta.to.shared.u64 t, %1; cvt.u32.u64 %0, t; }" : "=r"(a) : "l"(p));
    return a;
}
__device__ __forceinline__ void ldsm4(uint32_t* r, uint32_t a) {
    asm volatile("ldmatrix.sync.aligned.m8n8.x4.shared.b16 {%0,%1,%2,%3}, [%4];"
        : "=r"(r[0]), "=r"(r[1]), "=r"(r[2]), "=r"(r[3]) : "r"(a));
}
__device__ __forceinline__ void ldsm2(uint32_t& r0, uint32_t& r1, uint32_t a) {
    asm volatile("ldmatrix.sync.aligned.m8n8.x2.shared.b16 {%0,%1}, [%2];"
        : "=r"(r0), "=r"(r1) : "r"(a));
}
__device__ __forceinline__ void mma_bf16(float* c, const uint32_t* a, uint32_t b0, uint32_t b1) {
    asm volatile(
        "mma.sync.aligned.m16n8k16.row.col.f32.bf16.bf16.f32 "
        "{%0,%1,%2,%3}, {%4,%5,%6,%7}, {%8,%9}, {%0,%1,%2,%3};\n"
        : "+f"(c[0]), "+f"(c[1]), "+f"(c[2]), "+f"(c[3])
        : "r"(a[0]), "r"(a[1]), "r"(a[2]), "r"(a[3]), "r"(b0), "r"(b1));
}
__device__ __forceinline__ uint32_t pk(bf16 a, bf16 b) {
    __nv_bfloat162 t; t.x = a; t.y = b; return *(uint32_t*)&t;
}
__device__ __forceinline__ void splitpack(float v0, float v1, uint32_t& h, uint32_t& l) {
    bf16 h0 = __float2bfloat16(v0), h1 = __float2bfloat16(v1);
    bf16 l0 = __float2bfloat16(v0 - __bfloat162float(h0));
    bf16 l1 = __float2bfloat16(v1 - __bfloat162float(h1));
    h = pk(h0, h1); l = pk(l0, l1);
}

// ---------------- prep kernels ----------------
__global__ void prep_T(const float* CONST src, bf16* CONST dh, bf16* CONST dl,
                       int K, int N, int skip32)
{
    int idx = blockIdx.x * 256 + threadIdx.x;
    if (idx >= K * N) return;
    int k = idx % K, n = idx / K;
    int sr = (skip32 && k >= 32) ? k + 4 : k;
    float v = src[(size_t)sr * N + n];
    bf16 h = __float2bfloat16(v);
    dh[idx] = h;
    dl[idx] = __float2bfloat16(v - __bfloat162float(h));
}

__global__ void prep_states(const float* CONST s)
{
    int idx = blockIdx.x * 256 + threadIdx.x;
    if (idx >= NN * D_) return;
    float v = s[idx];
    bf16 h = __float2bfloat16(v);
    bf16 l = __float2bfloat16(v - __bfloat162float(h));
    gSTh[idx] = h; gSTl[idx] = l;
    int r = idx >> 5, c = idx & 31;
    gA4h[r * K4 + c] = h;
    gA4l[r * K4 + c] = l;
}

// ---------------- edge A materialization: relu(P+Q) split ----------------
__global__ __launch_bounds__(256) void esplit(int edgeOff)
{
    int gi = blockIdx.x * 256 + threadIdx.x;
    int e = edgeOff + (gi >> 6);
    int cg = (gi & 63) * 8;
    int node = e / EPN;
    int jj = e - node * EPN;
    int i = node % KO;
    int j = jj + (jj >= i ? 1 : 0);
    int cn = node - i + j;

    bf16 a[8], b[8], c2[8], d2[8], oh[8], ol[8];
    *(uint4*)a  = *(const uint4*)(gPh + (size_t)node * H_ + cg);
    *(uint4*)b  = *(const uint4*)(gPl + (size_t)node * H_ + cg);
    *(uint4*)c2 = *(const uint4*)(gQh + (size_t)cn * H_ + cg);
    *(uint4*)d2 = *(const uint4*)(gQl + (size_t)cn * H_ + cg);
    #pragma unroll
    for (int u = 0; u < 8; u++) {
        float v = (__bfloat162float(a[u]) + __bfloat162float(b[u]))
                + (__bfloat162float(c2[u]) + __bfloat162float(d2[u]));
        v = fmaxf(v, 0.f);
        oh[u] = __float2bfloat16(v);
        ol[u] = __float2bfloat16(v - __bfloat162float(oh[u]));
    }
    *(uint4*)(gEh + (size_t)e * H_ + cg) = *(const uint4*)oh;
    *(uint4*)(gEl + (size_t)e * H_ + cg) = *(const uint4*)ol;
}

// ---------------- pure split-bf16 mma.sync GEMM (pre-split A and B) ----------------
// MODE 0: gP planes = ST@w0 + eb1            (K=32)
// MODE 1: gQ planes = ST@w1                  (K=32)
// MODE 2: gH2 fp32  = E@w2 + eb2             (K=512, sliced)
// MODE 3: gA4[:,32:] = S@w3 + 9*eb3          (K=512)
// MODE 4: gN1 planes = relu(A4@w4 + nb1+row) (K=544)
// MODE 5: gN2r fp32 = N1@w5 + nb2            (K=512)
static constexpr int LDP = 40;

template <int MODE>
__global__ __launch_bounds__(256)
void tg(const bf16* CONST Ah_, const bf16* CONST Al_,
        const bf16* CONST Bh_, const bf16* CONST Bl_,
        const float* CONST bias, const int* CONST act,
        const float* CONST nw1full, int rowOff)
{
    constexpr int KT = (MODE <= 1) ? 32 : (MODE == 4 ? K4 : 512);
    constexpr int NC = KT / 32;
    __shared__ __align__(16) bf16 sAh[128 * LDP], sAl[128 * LDP];
    __shared__ __align__(16) bf16 sBh[128 * LDP], sBl[128 * LDP];

    const int tid = threadIdx.x, warp = tid >> 5, lane = tid & 31;
    const int rowBase = rowOff + blockIdx.y * 128;
    const int colBase = blockIdx.x * 128;
    const int fr = tid >> 1, fks = (tid & 1) * 16;

    const bf16* pAh = Ah_ + (size_t)(rowBase + fr) * KT + fks;
    const bf16* pAl = Al_ + (size_t)(rowBase + fr) * KT + fks;
    const bf16* pBh = Bh_ + (size_t)(colBase + fr) * KT + fks;
    const bf16* pBl = Bl_ + (size_t)(colBase + fr) * KT + fks;

    uint4 st[8];
    auto ldg = [&](int k0) {
        st[0] = *(const uint4*)(pAh + k0); st[1] = *(const uint4*)(pAh + k0 + 8);
        st[2] = *(const uint4*)(pAl + k0); st[3] = *(const uint4*)(pAl + k0 + 8);
        st[4] = *(const uint4*)(pBh + k0); st[5] = *(const uint4*)(pBh + k0 + 8);
        st[6] = *(const uint4*)(pBl + k0); st[7] = *(const uint4*)(pBl + k0 + 8);
    };
    const int sb = fr * LDP + fks;
    auto sts = [&]() {
        *(uint4*)&sAh[sb] = st[0]; *(uint4*)&sAh[sb + 8] = st[1];
        *(uint4*)&sAl[sb] = st[2]; *(uint4*)&sAl[sb + 8] = st[3];
        *(uint4*)&sBh[sb] = st[4]; *(uint4*)&sBh[sb + 8] = st[5];
        *(uint4*)&sBl[sb] = st[6]; *(uint4*)&sBl[sb + 8] = st[7];
    };

    const int wm = warp >> 2, wn = warp & 3;     // 2x4 warps, tile 64x32
    const int la_row = lane & 15, la_sel = lane >> 4;
    const int lb_row = lane & 7,  lb_sel = (lane >> 3) & 1;
    const uint32_t uAh = s2u(sAh), uAl = s2u(sAl), uBh = s2u(sBh), uBl = s2u(sBl);

    float acc[4][4][4];
    #pragma unroll
    for (int a = 0; a < 4; a++)
        #pragma unroll
        for (int b = 0; b < 4; b++)
            #pragma unroll
            for (int c = 0; c < 4; c++) acc[a][b][c] = 0.f;

    ldg(0);
    for (int c = 0; c < NC; c++) {
        sts();
        __syncthreads();
        if (c + 1 < NC) ldg((c + 1) * 32);

        #pragma unroll
        for (int kf = 0; kf < 2; kf++) {
            const int kb = kf * 16;
            uint32_t ah[4][4], al[4][4];
            #pragma unroll
            for (int mt = 0; mt < 4; mt++) {
                const uint32_t ra =
                    (uint32_t)(((wm * 64 + mt * 16 + la_row) * LDP + kb + la_sel * 8) * 2);
                ldsm4(ah[mt], uAh + ra);
                ldsm4(al[mt], uAl + ra);
            }
            #pragma unroll
            for (int nt = 0; nt < 4; nt++) {
                const uint32_t rb =
                    (uint32_t)(((wn * 32 + nt * 8 + lb_row) * LDP + kb + lb_sel * 8) * 2);
                uint32_t bh0, bh1, bl0, bl1;
                ldsm2(bh0, bh1, uBh + rb);
                ldsm2(bl0, bl1, uBl + rb);
                #pragma unroll
                for (int mt = 0; mt < 4; mt++) {
                    mma_bf16(acc[mt][nt], ah[mt], bh0, bh1);
                    mma_bf16(acc[mt][nt], ah[mt], bl0, bl1);
                    mma_bf16(acc[mt][nt], al[mt], bh0, bh1);
                }
            }
        }
        __syncthreads();
    }

    // ---- epilogue ----
    const int g = lane >> 2, tg2 = (lane & 3) * 2;
    #pragma unroll
    for (int mt = 0; mt < 4; mt++) {
        const int row0 = rowBase + wm * 64 + mt * 16 + g;
        const int row1 = row0 + 8;
        int a0r = 0, a1r = 0;
        if constexpr (MODE == 4) { a0r = act[row0 / KO]; a1r = act[row1 / KO]; }
        #pragma unroll
        for (int nt = 0; nt < 4; nt++) {
            const int col = colBase + wn * 32 + nt * 8 + tg2;
            float v0 = acc[mt][nt][0], v1 = acc[mt][nt][1];
            float v2 = acc[mt][nt][2], v3 = acc[mt][nt][3];
            if constexpr (MODE == 0 || MODE == 2 || MODE == 5) {
                float b0 = bias[col], b1 = bias[col + 1];
                v0 += b0; v1 += b1; v2 += b0; v3 += b1;
            }
            if constexpr (MODE == 3) {
                float b0 = 9.f * bias[col], b1 = 9.f * bias[col + 1];
                v0 += b0; v1 += b1; v2 += b0; v3 += b1;
            }
            if constexpr (MODE == 4) {
                float b0 = bias[col], b1 = bias[col + 1];
                const float* r0p = nw1full + (size_t)(32 + a0r) * H_;
                const float* r1p = nw1full + (size_t)(32 + a1r) * H_;
                v0 = fmaxf(v0 + b0 + r0p[col],     0.f);
                v1 = fmaxf(v1 + b1 + r0p[col + 1], 0.f);
                v2 = fmaxf(v2 + b0 + r1p[col],     0.f);
                v3 = fmaxf(v3 + b1 + r1p[col + 1], 0.f);
            }
            if constexpr (MODE == 2) {
                *(float2*)(gH2 + (size_t)row0 * H_ + col) = make_float2(v0, v1);
                *(float2*)(gH2 + (size_t)row1 * H_ + col) = make_float2(v2, v3);
            } else if constexpr (MODE == 5) {
                *(float2*)(gN2r + (size_t)row0 * H_ + col) = make_float2(v0, v1);
                *(float2*)(gN2r + (size_t)row1 * H_ + col) = make_float2(v2, v3);
            } else {
                uint32_t h01, l01, h23, l23;
                splitpack(v0, v1, h01, l01);
                splitpack(v2, v3, h23, l23);
                if constexpr (MODE == 0) {
                    *(uint32_t*)(gPh + (size_t)row0 * H_ + col) = h01;
                    *(uint32_t*)(gPl + (size_t)row0 * H_ + col) = l01;
                    *(uint32_t*)(gPh + (size_t)row1 * H_ + col) = h23;
                    *(uint32_t*)(gPl + (size_t)row1 * H_ + col) = l23;
                } else if constexpr (MODE == 1) {
                    *(uint32_t*)(gQh + (size_t)row0 * H_ + col) = h01;
                    *(uint32_t*)(gQl + (size_t)row0 * H_ + col) = l01;
                    *(uint32_t*)(gQh + (size_t)row1 * H_ + col) = h23;
                    *(uint32_t*)(gQl + (size_t)row1 * H_ + col) = l23;
                } else if constexpr (MODE == 3) {
                    *(uint32_t*)(gA4h + (size_t)row0 * K4 + 32 + col) = h01;
                    *(uint32_t*)(gA4l + (size_t)row0 * K4 + 32 + col) = l01;
                    *(uint32_t*)(gA4h + (size_t)row1 * K4 + 32 + col) = h23;
                    *(uint32_t*)(gA4l + (size_t)row1 * K4 + 32 + col) = l23;
                } else {  // MODE 4
                    *(uint32_t*)(gN1h + (size_t)row0 * H_ + col) = h01;
                    *(uint32_t*)(gN1l + (size_t)row0 * H_ + col) = l01;
                    *(uint32_t*)(gN1h + (size_t)row1 * H_ + col) = h23;
                    *(uint32_t*)(gN1l + (size_t)row1 * H_ + col) = l23;
                }
            }
        }
    }
}

// ---------------- LN + relu + 9-row sum -> split S planes ----------------
__global__ __launch_bounds__(256)
void ln_sum_k(const float* CONST g, const float* CONST bt, int nodeOff)
{
    const int tid = threadIdx.x, warp = tid >> 5, lane = tid & 31;
    const int n = nodeOff + blockIdx.x * 8 + warp;
    const float4* gg = (const float4*)g;
    const float4* bb = (const float4*)bt;
    float4 G[4], Bt[4], acc[4];
    #pragma unroll
    for (int j = 0; j < 4; j++) {
        G[j] = gg[lane + 32 * j];
        Bt[j] = bb[lane + 32 * j];
        acc[j] = make_float4(0.f, 0.f, 0.f, 0.f);
    }
    for (int e = 0; e < EPN; e++) {
        const float4* rp = (const float4*)(gH2 + (size_t)(n * EPN + e) * H_);
        float4 v[4];
        float s = 0.f, sq = 0.f;
        #pragma unroll
        for (int j = 0; j < 4; j++) {
            v[j] = rp[lane + 32 * j];
            s  += v[j].x + v[j].y + v[j].z + v[j].w;
            sq += v[j].x * v[j].x + v[j].y * v[j].y + v[j].z * v[j].z + v[j].w * v[j].w;
        }
        #pragma unroll
        for (int o = 16; o > 0; o >>= 1) {
            s  += __shfl_xor_sync(0xffffffff, s, o);
            sq += __shfl_xor_sync(0xffffffff, sq, o);
        }
        const float mean = s * (1.f / 512.f);
        const float rstd = rsqrtf(sq * (1.f / 512.f) - mean * mean + EPS);
        #pragma unroll
        for (int j = 0; j < 4; j++) {
            acc[j].x += fmaxf((v[j].x - mean) * rstd * G[j].x + Bt[j].x, 0.f);
            acc[j].y += fmaxf((v[j].y - mean) * rstd * G[j].y + Bt[j].y, 0.f);
            acc[j].z += fmaxf((v[j].z - mean) * rstd * G[j].z + Bt[j].z, 0.f);
            acc[j].w += fmaxf((v[j].w - mean) * rstd * G[j].w + Bt[j].w, 0.f);
        }
    }
    #pragma unroll
    for (int j = 0; j < 4; j++) {
        const int cb = (lane + 32 * j) * 4;
        uint32_t h01, l01, h23, l23;
        splitpack(acc[j].x, acc[j].y, h01, l01);
        splitpack(acc[j].z, acc[j].w, h23, l23);
        uint2 hv = make_uint2(h01, h23), lv = make_uint2(l01, l23);
        *(uint2*)(gSh + (size_t)n * H_ + cb) = hv;
        *(uint2*)(gSl + (size_t)n * H_ + cb) = lv;
    }
}

// ---------------- LN + relu of gN2r ----------------
__global__ __launch_bounds__(256)
void ln2_k(const float* CONST g, const float* CONST bt)
{
    const int tid = threadIdx.x, warp = tid >> 5, lane = tid & 31;
    const int n = blockIdx.x * 8 + warp;
    const float4* rp = (const float4*)(gN2r + (size_t)n * H_);
    float4 v[4];
    float s = 0.f, sq = 0.f;
    #pragma unroll
    for (int j = 0; j < 4; j++) {
        v[j] = rp[lane + 32 * j];
        s  += v[j].x + v[j].y + v[j].z + v[j].w;
        sq += v[j].x * v[j].x + v[j].y * v[j].y + v[j].z * v[j].z + v[j].w * v[j].w;
    }
    #pragma unroll
    for (int o = 16; o > 0; o >>= 1) {
        s  += __shfl_xor_sync(0xffffffff, s, o);
        sq += __shfl_xor_sync(0xffffffff, sq, o);
    }
    const float mean = s * (1.f / 512.f);
    const float rstd = rsqrtf(sq * (1.f / 512.f) - mean * mean + EPS);
    float4* op = (float4*)(gN2 + (size_t)n * H_);
    #pragma unroll
    for (int j = 0; j < 4; j++) {
        const int c = (lane + 32 * j) * 4;
        float4 o4;
        o4.x = fmaxf((v[j].x - mean) * rstd * g[c]     + bt[c],     0.f);
        o4.y = fmaxf((v[j].y - mean) * rstd * g[c + 1] + bt[c + 1], 0.f);
        o4.z = fmaxf((v[j].z - mean) * rstd * g[c + 2] + bt[c + 2], 0.f);
        o4.w = fmaxf((v[j].w - mean) * rstd * g[c + 3] + bt[c + 3], 0.f);
        op[lane + 32 * j] = o4;
    }
}

// ---------------- out = gN2 @ nw3 + nb3 ----------------
__global__ __launch_bounds__(256)
void n3_k(const float* CONST w3, const float* CONST b3, float* CONST out)
{
    __shared__ float xs[8][H_];
    const int r0 = blockIdx.x * 8;
    const int t = threadIdx.x;
    for (int i = t; i < 8 * H_; i += 256)
        xs[i >> 9][i & 511] = gN2[(size_t)(r0 + (i >> 9)) * H_ + (i & 511)];
    __syncthreads();
    const int lr = t >> 5, c = t & 31;
    float accv = b3[c];
    #pragma unroll 8
    for (int k = 0; k < H_; k++)
        accv = fmaf(xs[lr][k], w3[k * D_ + c], accv);
    out[(size_t)(r0 + lr) * D_ + c] = accv;
}

// ---------------- launch ----------------
extern "C" void kernel_launch(void* const* d_in, const int* in_sizes, int n_in,
                              void* d_out, int out_size)
{
    (void)in_sizes; (void)n_in; (void)out_size;
    const float* states = (const float*)d_in[0];
    const int*   action = (const int*)  d_in[1];
    const float* ew1 = (const float*)d_in[2];
    const float* eb1 = (const float*)d_in[3];
    const float* ew2 = (const float*)d_in[4];
    const float* eb2 = (const float*)d_in[5];
    const float* eg  = (const float*)d_in[6];
    const float* ebt = (const float*)d_in[7];
    const float* ew3 = (const float*)d_in[8];
    const float* eb3 = (const float*)d_in[9];
    const float* nw1 = (const float*)d_in[10];
    const float* nb1 = (const float*)d_in[11];
    const float* nw2 = (const float*)d_in[12];
    const float* nb2 = (const float*)d_in[13];
    const float* ng  = (const float*)d_in[14];
    const float* nbt = (const float*)d_in[15];
    const float* nw3 = (const float*)d_in[16];
    const float* nb3 = (const float*)d_in[17];
    float* out = (float*)d_out;

    bf16 *w0h, *w0l, *w1h, *w1l, *w2h, *w2l, *w3h, *w3l, *w4h, *w4l, *w5h, *w5l;
    bf16 *sth, *stl, *eh, *el, *sh, *sl, *a4h, *a4l, *n1h, *n1l;
    cudaGetSymbolAddress((void**)&w0h, gW0h); cudaGetSymbolAddress((void**)&w0l, gW0l);
    cudaGetSymbolAddress((void**)&w1h, gW1h); cudaGetSymbolAddress((void**)&w1l, gW1l);
    cudaGetSymbolAddress((void**)&w2h, gW2h); cudaGetSymbolAddress((void**)&w2l, gW2l);
    cudaGetSymbolAddress((void**)&w3h, gW3h); cudaGetSymbolAddress((void**)&w3l, gW3l);
    cudaGetSymbolAddress((void**)&w4h, gW4h); cudaGetSymbolAddress((void**)&w4l, gW4l);
    cudaGetSymbolAddress((void**)&w5h, gW5h); cudaGetSymbolAddress((void**)&w5l, gW5l);
    cudaGetSymbolAddress((void**)&sth, gSTh); cudaGetSymbolAddress((void**)&stl, gSTl);
    cudaGetSymbolAddress((void**)&eh,  gEh);  cudaGetSymbolAddress((void**)&el,  gEl);
    cudaGetSymbolAddress((void**)&sh,  gSh);  cudaGetSymbolAddress((void**)&sl,  gSl);
    cudaGetSymbolAddress((void**)&a4h, gA4h); cudaGetSymbolAddress((void**)&a4l, gA4l);
    cudaGetSymbolAddress((void**)&n1h, gN1h); cudaGetSymbolAddress((void**)&n1l, gN1l);

    auto gsz = [](int e) { return (e + 255) / 256; };
    prep_T<<<gsz(H_ * 32), 256>>>(ew1,           w0h, w0l, 32,  H_, 0);
    prep_T<<<gsz(H_ * 32), 256>>>(ew1 + 32 * H_, w1h, w1l, 32,  H_, 0);
    prep_T<<<gsz(H_ * H_), 256>>>(ew2,           w2h, w2l, H_,  H_, 0);
    prep_T<<<gsz(H_ * H_), 256>>>(ew3,           w3h, w3l, H_,  H_, 0);
    prep_T<<<gsz(H_ * K4), 256>>>(nw1,           w4h, w4l, K4,  H_, 1);
    prep_T<<<gsz(H_ * H_), 256>>>(nw2,           w5h, w5l, H_,  H_, 0);
    prep_states<<<gsz(NN * D_), 256>>>(states);

    dim3 blk(256);
    tg<0><<<dim3(4, NN / 128), blk>>>(sth, stl, w0h, w0l, eb1, nullptr, nullptr, 0);
    tg<1><<<dim3(4, NN / 128), blk>>>(sth, stl, w1h, w1l, nullptr, nullptr, nullptr, 0);

    for (int s = 0; s < NSLICE; s++) {
        esplit<<<ESL * 64 / 256, 256>>>(s * ESL);
        tg<2><<<dim3(4, ESL / 128), blk>>>(eh, el, w2h, w2l, eb2, nullptr, nullptr, s * ESL);
        ln_sum_k<<<NSL / 8, 256>>>(eg, ebt, s * NSL);
    }

    tg<3><<<dim3(4, NN / 128), blk>>>(sh,  sl,  w3h, w3l, eb3, nullptr, nullptr, 0);
    tg<4><<<dim3(4, NN / 128), blk>>>(a4h, a4l, w4h, w4l, nb1, action, nw1, 0);
    tg<5><<<dim3(4, NN / 128), blk>>>(n1h, n1l, w5h, w5l, nb2, nullptr, nullptr, 0);
    ln2_k<<<NN / 8, 256>>>(ng, nbt);
    n3_k<<<NN / 8, 256>>>(nw3, nb3, out);
}

// round 6
// speedup vs baseline: 2.8586x; 1.0357x over previous
#include <cuda_runtime.h>
#include <cuda_bf16.h>
#include <cstdint>

#define CONST __restrict__
using bf16 = __nv_bfloat16;

static constexpr int B_  = 1024;
static constexpr int KO  = 10;
static constexpr int D_  = 32;
static constexpr int H_  = 512;
static constexpr int NN  = B_ * KO;     // 10240
static constexpr int EPN = KO - 1;      // 9
static constexpr int NE  = NN * EPN;    // 92160
static constexpr float EPS = 1e-5f;
static constexpr int K4  = 544;

static constexpr int NSLICE = 4;
static constexpr int ESL = NE / NSLICE;
static constexpr int NSL = NN / NSLICE;

// ---------------- scratch planes ----------------
__device__ __align__(16) bf16 gSTh[NN * D_],  gSTl[NN * D_];
__device__ __align__(16) bf16 gPh [NN * H_],  gPl [NN * H_];
__device__ __align__(16) bf16 gQh [NN * H_],  gQl [NN * H_];
__device__ __align__(16) bf16 gEh [(size_t)NE * H_], gEl[(size_t)NE * H_];
__device__ float gH2 [(size_t)NE * H_];
__device__ __align__(16) bf16 gSh [NN * H_],  gSl [NN * H_];
__device__ __align__(16) bf16 gA4h[NN * K4],  gA4l[NN * K4];
__device__ __align__(16) bf16 gN1h[NN * H_],  gN1l[NN * H_];
__device__ float gN2r[NN * H_], gN2[NN * H_];

// split transposed weights [N][K]
__device__ __align__(16) bf16 gW0h[H_ * 32],  gW0l[H_ * 32];
__device__ __align__(16) bf16 gW1h[H_ * 32],  gW1l[H_ * 32];
__device__ __align__(16) bf16 gW2h[H_ * H_],  gW2l[H_ * H_];
__device__ __align__(16) bf16 gW3h[H_ * H_],  gW3l[H_ * H_];
__device__ __align__(16) bf16 gW4h[H_ * K4],  gW4l[H_ * K4];
__device__ __align__(16) bf16 gW5h[H_ * H_],  gW5l[H_ * H_];

// ---------------- helpers ----------------
__device__ __forceinline__ uint32_t s2u(const void* p) {
    uint32_t a;
    asm("{ .reg .u64 t; cvta.to.shared.u64 t, %1; cvt.u32.u64 %0, t; }" : "=r"(a) : "l"(p));
    return a;
}
__device__ __forceinline__ void cp16(uint32_t s, const void* g) {
    asm volatile("cp.async.cg.shared.global [%0], [%1], 16;" :: "r"(s), "l"(g));
}
__device__ __forceinline__ void ldsm4(uint32_t* r, uint32_t a) {
    asm volatile("ldmatrix.sync.aligned.m8n8.x4.shared.b16 {%0,%1,%2,%3}, [%4];"
        : "=r"(r[0]), "=r"(r[1]), "=r"(r[2]), "=r"(r[3]) : "r"(a));
}
__device__ __forceinline__ void ldsm2(uint32_t& r0, uint32_t& r1, uint32_t a) {
    asm volatile("ldmatrix.sync.aligned.m8n8.x2.shared.b16 {%0,%1}, [%2];"
        : "=r"(r0), "=r"(r1) : "r"(a));
}
__device__ __forceinline__ void mma_bf16(float* c, const uint32_t* a, uint32_t b0, uint32_t b1) {
    asm volatile(
        "mma.sync.aligned.m16n8k16.row.col.f32.bf16.bf16.f32 "
        "{%0,%1,%2,%3}, {%4,%5,%6,%7}, {%8,%9}, {%0,%1,%2,%3};\n"
        : "+f"(c[0]), "+f"(c[1]), "+f"(c[2]), "+f"(c[3])
        : "r"(a[0]), "r"(a[1]), "r"(a[2]), "r"(a[3]), "r"(b0), "r"(b1));
}
__device__ __forceinline__ uint32_t pk(bf16 a, bf16 b) {
    __nv_bfloat162 t; t.x = a; t.y = b; return *(uint32_t*)&t;
}
__device__ __forceinline__ void splitpack(float v0, float v1, uint32_t& h, uint32_t& l) {
    bf16 h0 = __float2bfloat16(v0), h1 = __float2bfloat16(v1);
    bf16 l0 = __float2bfloat16(v0 - __bfloat162float(h0));
    bf16 l1 = __float2bfloat16(v1 - __bfloat162float(h1));
    h = pk(h0, h1); l = pk(l0, l1);
}

// ---------------- single merged weight-prep kernel ----------------
__global__ void prep_all(const float* CONST ew1, const float* CONST ew2,
                         const float* CONST ew3, const float* CONST nw1,
                         const float* CONST nw2)
{
    int idx = blockIdx.x * 256 + threadIdx.x;
    if (idx >= 1097728) return;
    const float* src; bf16 *dh, *dl; int K, off, skip = 0;
    if      (idx < 16384)  { src = ew1;            dh = gW0h; dl = gW0l; K = 32;  off = 0; }
    else if (idx < 32768)  { src = ew1 + 32 * H_;  dh = gW1h; dl = gW1l; K = 32;  off = 16384; }
    else if (idx < 294912) { src = ew2;            dh = gW2h; dl = gW2l; K = 512; off = 32768; }
    else if (idx < 557056) { src = ew3;            dh = gW3h; dl = gW3l; K = 512; off = 294912; }
    else if (idx < 835584) { src = nw1;            dh = gW4h; dl = gW4l; K = K4;  off = 557056; skip = 1; }
    else                   { src = nw2;            dh = gW5h; dl = gW5l; K = 512; off = 835584; }
    idx -= off;
    int k = idx % K, n = idx / K;
    int sr = (skip && k >= 32) ? k + 4 : k;
    float v = src[(size_t)sr * H_ + n];
    bf16 h = __float2bfloat16(v);
    dh[idx] = h;
    dl[idx] = __float2bfloat16(v - __bfloat162float(h));
}

__global__ void prep_states(const float* CONST s)
{
    int idx = blockIdx.x * 256 + threadIdx.x;
    if (idx >= NN * D_) return;
    float v = s[idx];
    bf16 h = __float2bfloat16(v);
    bf16 l = __float2bfloat16(v - __bfloat162float(h));
    gSTh[idx] = h; gSTl[idx] = l;
    int r = idx >> 5, c = idx & 31;
    gA4h[r * K4 + c] = h;
    gA4l[r * K4 + c] = l;
}

// ---------------- edge A materialization: relu(P+Q) split ----------------
__global__ __launch_bounds__(256) void esplit(int edgeOff)
{
    int gi = blockIdx.x * 256 + threadIdx.x;
    int e = edgeOff + (gi >> 6);
    int cg = (gi & 63) * 8;
    int node = e / EPN;
    int jj = e - node * EPN;
    int i = node % KO;
    int j = jj + (jj >= i ? 1 : 0);
    int cn = node - i + j;

    bf16 a[8], b[8], c2[8], d2[8], oh[8], ol[8];
    *(uint4*)a  = *(const uint4*)(gPh + (size_t)node * H_ + cg);
    *(uint4*)b  = *(const uint4*)(gPl + (size_t)node * H_ + cg);
    *(uint4*)c2 = *(const uint4*)(gQh + (size_t)cn * H_ + cg);
    *(uint4*)d2 = *(const uint4*)(gQl + (size_t)cn * H_ + cg);
    #pragma unroll
    for (int u = 0; u < 8; u++) {
        float v = (__bfloat162float(a[u]) + __bfloat162float(b[u]))
                + (__bfloat162float(c2[u]) + __bfloat162float(d2[u]));
        v = fmaxf(v, 0.f);
        oh[u] = __float2bfloat16(v);
        ol[u] = __float2bfloat16(v - __bfloat162float(oh[u]));
    }
    *(uint4*)(gEh + (size_t)e * H_ + cg) = *(const uint4*)oh;
    *(uint4*)(gEl + (size_t)e * H_ + cg) = *(const uint4*)ol;
}

// ---------------- cp.async double-buffered split-bf16 mma GEMM ----------------
static constexpr int LDP = 40;
static constexpr int SZA = 128 * LDP * 2;        // 10240 B per array
static constexpr int STG = 4 * SZA;              // 40960 B per stage
static constexpr int SMEM_SZ = 2 * STG;          // 81920 B

template <int MODE>
__global__ __launch_bounds__(256, 2)
void tg(const bf16* CONST Ah_, const bf16* CONST Al_,
        const bf16* CONST Bh_, const bf16* CONST Bl_,
        const float* CONST bias, const int* CONST act,
        const float* CONST nw1full, int rowOff)
{
    constexpr int KT = (MODE <= 1) ? 32 : (MODE == 4 ? K4 : 512);
    constexpr int NC = KT / 32;
    extern __shared__ char smraw[];
    const uint32_t sbase = s2u(smraw);

    const int tid = threadIdx.x, warp = tid >> 5, lane = tid & 31;
    const int rowBase = rowOff + blockIdx.y * 128;
    const int colBase = blockIdx.x * 128;
    const int fr = tid >> 1, fks = (tid & 1) * 16;

    const bf16* pAh = Ah_ + (size_t)(rowBase + fr) * KT + fks;
    const bf16* pAl = Al_ + (size_t)(rowBase + fr) * KT + fks;
    const bf16* pBh = Bh_ + (size_t)(colBase + fr) * KT + fks;
    const bf16* pBl = Bl_ + (size_t)(colBase + fr) * KT + fks;

    const uint32_t wb = sbase + (fr * LDP + fks) * 2;
    auto ldgsts = [&](int stg, int k0) {
        const uint32_t d = wb + stg * STG;
        cp16(d,                pAh + k0);  cp16(d + 16,            pAh + k0 + 8);
        cp16(d + SZA,          pAl + k0);  cp16(d + SZA + 16,      pAl + k0 + 8);
        cp16(d + 2 * SZA,      pBh + k0);  cp16(d + 2 * SZA + 16,  pBh + k0 + 8);
        cp16(d + 3 * SZA,      pBl + k0);  cp16(d + 3 * SZA + 16,  pBl + k0 + 8);
        asm volatile("cp.async.commit_group;");
    };

    const int wm = warp >> 2, wn = warp & 3;     // 2x4 warps, tile 64x32
    const int la_row = lane & 15, la_sel = lane >> 4;
    const int lb_row = lane & 7,  lb_sel = (lane >> 3) & 1;

    float acc[4][4][4];
    #pragma unroll
    for (int a = 0; a < 4; a++)
        #pragma unroll
        for (int b = 0; b < 4; b++)
            #pragma unroll
            for (int c = 0; c < 4; c++) acc[a][b][c] = 0.f;

    ldgsts(0, 0);
    for (int c = 0; c < NC; c++) {
        if (c + 1 < NC) {
            ldgsts((c + 1) & 1, (c + 1) * 32);
            asm volatile("cp.async.wait_group 1;");
        } else {
            asm volatile("cp.async.wait_group 0;");
        }
        __syncthreads();

        const uint32_t uA = sbase + (c & 1) * STG;
        const uint32_t uB = uA + 2 * SZA;
        #pragma unroll
        for (int kf = 0; kf < 2; kf++) {
            const int kb = kf * 16;
            uint32_t ah[4][4], al[4][4];
            #pragma unroll
            for (int mt = 0; mt < 4; mt++) {
                const uint32_t ra =
                    (uint32_t)(((wm * 64 + mt * 16 + la_row) * LDP + kb + la_sel * 8) * 2);
                ldsm4(ah[mt], uA + ra);
                ldsm4(al[mt], uA + SZA + ra);
            }
            #pragma unroll
            for (int nt = 0; nt < 4; nt++) {
                const uint32_t rb =
                    (uint32_t)(((wn * 32 + nt * 8 + lb_row) * LDP + kb + lb_sel * 8) * 2);
                uint32_t bh0, bh1, bl0, bl1;
                ldsm2(bh0, bh1, uB + rb);
                ldsm2(bl0, bl1, uB + SZA + rb);
                #pragma unroll
                for (int mt = 0; mt < 4; mt++) {
                    mma_bf16(acc[mt][nt], ah[mt], bh0, bh1);
                    mma_bf16(acc[mt][nt], ah[mt], bl0, bl1);
                    mma_bf16(acc[mt][nt], al[mt], bh0, bh1);
                }
            }
        }
        __syncthreads();
    }

    // ---- epilogue ----
    const int g = lane >> 2, tg2 = (lane & 3) * 2;
    #pragma unroll
    for (int mt = 0; mt < 4; mt++) {
        const int row0 = rowBase + wm * 64 + mt * 16 + g;
        const int row1 = row0 + 8;
        int a0r = 0, a1r = 0;
        if constexpr (MODE == 4) { a0r = act[row0 / KO]; a1r = act[row1 / KO]; }
        #pragma unroll
        for (int nt = 0; nt < 4; nt++) {
            const int col = colBase + wn * 32 + nt * 8 + tg2;
            float v0 = acc[mt][nt][0], v1 = acc[mt][nt][1];
            float v2 = acc[mt][nt][2], v3 = acc[mt][nt][3];
            if constexpr (MODE == 0 || MODE == 2 || MODE == 5) {
                float b0 = bias[col], b1 = bias[col + 1];
                v0 += b0; v1 += b1; v2 += b0; v3 += b1;
            }
            if constexpr (MODE == 3) {
                float b0 = 9.f * bias[col], b1 = 9.f * bias[col + 1];
                v0 += b0; v1 += b1; v2 += b0; v3 += b1;
            }
            if constexpr (MODE == 4) {
                float b0 = bias[col], b1 = bias[col + 1];
                const float* r0p = nw1full + (size_t)(32 + a0r) * H_;
                const float* r1p = nw1full + (size_t)(32 + a1r) * H_;
                v0 = fmaxf(v0 + b0 + r0p[col],     0.f);
                v1 = fmaxf(v1 + b1 + r0p[col + 1], 0.f);
                v2 = fmaxf(v2 + b0 + r1p[col],     0.f);
                v3 = fmaxf(v3 + b1 + r1p[col + 1], 0.f);
            }
            if constexpr (MODE == 2) {
                *(float2*)(gH2 + (size_t)row0 * H_ + col) = make_float2(v0, v1);
                *(float2*)(gH2 + (size_t)row1 * H_ + col) = make_float2(v2, v3);
            } else if constexpr (MODE == 5) {
                *(float2*)(gN2r + (size_t)row0 * H_ + col) = make_float2(v0, v1);
                *(float2*)(gN2r + (size_t)row1 * H_ + col) = make_float2(v2, v3);
            } else {
                uint32_t h01, l01, h23, l23;
                splitpack(v0, v1, h01, l01);
                splitpack(v2, v3, h23, l23);
                if constexpr (MODE == 0) {
                    *(uint32_t*)(gPh + (size_t)row0 * H_ + col) = h01;
                    *(uint32_t*)(gPl + (size_t)row0 * H_ + col) = l01;
                    *(uint32_t*)(gPh + (size_t)row1 * H_ + col) = h23;
                    *(uint32_t*)(gPl + (size_t)row1 * H_ + col) = l23;
                } else if constexpr (MODE == 1) {
                    *(uint32_t*)(gQh + (size_t)row0 * H_ + col) = h01;
                    *(uint32_t*)(gQl + (size_t)row0 * H_ + col) = l01;
                    *(uint32_t*)(gQh + (size_t)row1 * H_ + col) = h23;
                    *(uint32_t*)(gQl + (size_t)row1 * H_ + col) = l23;
                } else if constexpr (MODE == 3) {
                    *(uint32_t*)(gA4h + (size_t)row0 * K4 + 32 + col) = h01;
                    *(uint32_t*)(gA4l + (size_t)row0 * K4 + 32 + col) = l01;
                    *(uint32_t*)(gA4h + (size_t)row1 * K4 + 32 + col) = h23;
                    *(uint32_t*)(gA4l + (size_t)row1 * K4 + 32 + col) = l23;
                } else {
                    *(uint32_t*)(gN1h + (size_t)row0 * H_ + col) = h01;
                    *(uint32_t*)(gN1l + (size_t)row0 * H_ + col) = l01;
                    *(uint32_t*)(gN1h + (size_t)row1 * H_ + col) = h23;
                    *(uint32_t*)(gN1l + (size_t)row1 * H_ + col) = l23;
                }
            }
        }
    }
}

// ---------------- LN + relu + 9-row sum -> split S planes ----------------
__global__ __launch_bounds__(256)
void ln_sum_k(const float* CONST g, const float* CONST bt, int nodeOff)
{
    const int tid = threadIdx.x, warp = tid >> 5, lane = tid & 31;
    const int n = nodeOff + blockIdx.x * 8 + warp;
    const float4* gg = (const float4*)g;
    const float4* bb = (const float4*)bt;
    float4 G[4], Bt[4], acc[4];
    #pragma unroll
    for (int j = 0; j < 4; j++) {
        G[j] = gg[lane + 32 * j];
        Bt[j] = bb[lane + 32 * j];
        acc[j] = make_float4(0.f, 0.f, 0.f, 0.f);
    }
    for (int e = 0; e < EPN; e++) {
        const float4* rp = (const float4*)(gH2 + (size_t)(n * EPN + e) * H_);
        float4 v[4];
        float s = 0.f, sq = 0.f;
        #pragma unroll
        for (int j = 0; j < 4; j++) {
            v[j] = rp[lane + 32 * j];
            s  += v[j].x + v[j].y + v[j].z + v[j].w;
            sq += v[j].x * v[j].x + v[j].y * v[j].y + v[j].z * v[j].z + v[j].w * v[j].w;
        }
        #pragma unroll
        for (int o = 16; o > 0; o >>= 1) {
            s  += __shfl_xor_sync(0xffffffff, s, o);
            sq += __shfl_xor_sync(0xffffffff, sq, o);
        }
        const float mean = s * (1.f / 512.f);
        const float rstd = rsqrtf(sq * (1.f / 512.f) - mean * mean + EPS);
        #pragma unroll
        for (int j = 0; j < 4; j++) {
            acc[j].x += fmaxf((v[j].x - mean) * rstd * G[j].x + Bt[j].x, 0.f);
            acc[j].y += fmaxf((v[j].y - mean) * rstd * G[j].y + Bt[j].y, 0.f);
            acc[j].z += fmaxf((v[j].z - mean) * rstd * G[j].z + Bt[j].z, 0.f);
            acc[j].w += fmaxf((v[j].w - mean) * rstd * G[j].w + Bt[j].w, 0.f);
        }
    }
    #pragma unroll
    for (int j = 0; j < 4; j++) {
        const int cb = (lane + 32 * j) * 4;
        uint32_t h01, l01, h23, l23;
        splitpack(acc[j].x, acc[j].y, h01, l01);
        splitpack(acc[j].z, acc[j].w, h23, l23);
        *(uint2*)(gSh + (size_t)n * H_ + cb) = make_uint2(h01, h23);
        *(uint2*)(gSl + (size_t)n * H_ + cb) = make_uint2(l01, l23);
    }
}

// ---------------- LN + relu of gN2r ----------------
__global__ __launch_bounds__(256)
void ln2_k(const float* CONST g, const float* CONST bt)
{
    const int tid = threadIdx.x, warp = tid >> 5, lane = tid & 31;
    const int n = blockIdx.x * 8 + warp;
    const float4* rp = (const float4*)(gN2r + (size_t)n * H_);
    float4 v[4];
    float s = 0.f, sq = 0.f;
    #pragma unroll
    for (int j = 0; j < 4; j++) {
        v[j] = rp[lane + 32 * j];
        s  += v[j].x + v[j].y + v[j].z + v[j].w;
        sq += v[j].x * v[j].x + v[j].y * v[j].y + v[j].z * v[j].z + v[j].w * v[j].w;
    }
    #pragma unroll
    for (int o = 16; o > 0; o >>= 1) {
        s  += __shfl_xor_sync(0xffffffff, s, o);
        sq += __shfl_xor_sync(0xffffffff, sq, o);
    }
    const float mean = s * (1.f / 512.f);
    const float rstd = rsqrtf(sq * (1.f / 512.f) - mean * mean + EPS);
    float4* op = (float4*)(gN2 + (size_t)n * H_);
    #pragma unroll
    for (int j = 0; j < 4; j++) {
        const int c = (lane + 32 * j) * 4;
        float4 o4;
        o4.x = fmaxf((v[j].x - mean) * rstd * g[c]     + bt[c],     0.f);
        o4.y = fmaxf((v[j].y - mean) * rstd * g[c + 1] + bt[c + 1], 0.f);
        o4.z = fmaxf((v[j].z - mean) * rstd * g[c + 2] + bt[c + 2], 0.f);
        o4.w = fmaxf((v[j].w - mean) * rstd * g[c + 3] + bt[c + 3], 0.f);
        op[lane + 32 * j] = o4;
    }
}

// ---------------- out = gN2 @ nw3 + nb3 ----------------
__global__ __launch_bounds__(256)
void n3_k(const float* CONST w3, const float* CONST b3, float* CONST out)
{
    __shared__ float xs[8][H_];
    const int r0 = blockIdx.x * 8;
    const int t = threadIdx.x;
    for (int i = t; i < 8 * H_; i += 256)
        xs[i >> 9][i & 511] = gN2[(size_t)(r0 + (i >> 9)) * H_ + (i & 511)];
    __syncthreads();
    const int lr = t >> 5, c = t & 31;
    float accv = b3[c];
    #pragma unroll 8
    for (int k = 0; k < H_; k++)
        accv = fmaf(xs[lr][k], w3[k * D_ + c], accv);
    out[(size_t)(r0 + lr) * D_ + c] = accv;
}

// ---------------- launch ----------------
extern "C" void kernel_launch(void* const* d_in, const int* in_sizes, int n_in,
                              void* d_out, int out_size)
{
    (void)in_sizes; (void)n_in; (void)out_size;
    const float* states = (const float*)d_in[0];
    const int*   action = (const int*)  d_in[1];
    const float* ew1 = (const float*)d_in[2];
    const float* eb1 = (const float*)d_in[3];
    const float* ew2 = (const float*)d_in[4];
    const float* eb2 = (const float*)d_in[5];
    const float* eg  = (const float*)d_in[6];
    const float* ebt = (const float*)d_in[7];
    const float* ew3 = (const float*)d_in[8];
    const float* eb3 = (const float*)d_in[9];
    const float* nw1 = (const float*)d_in[10];
    const float* nb1 = (const float*)d_in[11];
    const float* nw2 = (const float*)d_in[12];
    const float* nb2 = (const float*)d_in[13];
    const float* ng  = (const float*)d_in[14];
    const float* nbt = (const float*)d_in[15];
    const float* nw3 = (const float*)d_in[16];
    const float* nb3 = (const float*)d_in[17];
    float* out = (float*)d_out;

    static bool attrSet = false;
    if (!attrSet) {
        cudaFuncSetAttribute(tg<0>, cudaFuncAttributeMaxDynamicSharedMemorySize, SMEM_SZ);
        cudaFuncSetAttribute(tg<1>, cudaFuncAttributeMaxDynamicSharedMemorySize, SMEM_SZ);
        cudaFuncSetAttribute(tg<2>, cudaFuncAttributeMaxDynamicSharedMemorySize, SMEM_SZ);
        cudaFuncSetAttribute(tg<3>, cudaFuncAttributeMaxDynamicSharedMemorySize, SMEM_SZ);
        cudaFuncSetAttribute(tg<4>, cudaFuncAttributeMaxDynamicSharedMemorySize, SMEM_SZ);
        cudaFuncSetAttribute(tg<5>, cudaFuncAttributeMaxDynamicSharedMemorySize, SMEM_SZ);
        attrSet = true;
    }

    bf16 *w0h, *w0l, *w1h, *w1l, *w2h, *w2l, *w3h, *w3l, *w4h, *w4l, *w5h, *w5l;
    bf16 *sth, *stl, *eh, *el, *sh, *sl, *a4h, *a4l, *n1h, *n1l;
    cudaGetSymbolAddress((void**)&w0h, gW0h); cudaGetSymbolAddress((void**)&w0l, gW0l);
    cudaGetSymbolAddress((void**)&w1h, gW1h); cudaGetSymbolAddress((void**)&w1l, gW1l);
    cudaGetSymbolAddress((void**)&w2h, gW2h); cudaGetSymbolAddress((void**)&w2l, gW2l);
    cudaGetSymbolAddress((void**)&w3h, gW3h); cudaGetSymbolAddress((void**)&w3l, gW3l);
    cudaGetSymbolAddress((void**)&w4h, gW4h); cudaGetSymbolAddress((void**)&w4l, gW4l);
    cudaGetSymbolAddress((void**)&w5h, gW5h); cudaGetSymbolAddress((void**)&w5l, gW5l);
    cudaGetSymbolAddress((void**)&sth, gSTh); cudaGetSymbolAddress((void**)&stl, gSTl);
    cudaGetSymbolAddress((void**)&eh,  gEh);  cudaGetSymbolAddress((void**)&el,  gEl);
    cudaGetSymbolAddress((void**)&sh,  gSh);  cudaGetSymbolAddress((void**)&sl,  gSl);
    cudaGetSymbolAddress((void**)&a4h, gA4h); cudaGetSymbolAddress((void**)&a4l, gA4l);
    cudaGetSymbolAddress((void**)&n1h, gN1h); cudaGetSymbolAddress((void**)&n1l, gN1l);

    prep_all<<<(1097728 + 255) / 256, 256>>>(ew1, ew2, ew3, nw1, nw2);
    prep_states<<<(NN * D_ + 255) / 256, 256>>>(states);

    dim3 blk(256);
    tg<0><<<dim3(4, NN / 128), blk, SMEM_SZ>>>(sth, stl, w0h, w0l, eb1, nullptr, nullptr, 0);
    tg<1><<<dim3(4, NN / 128), blk, SMEM_SZ>>>(sth, stl, w1h, w1l, nullptr, nullptr, nullptr, 0);

    for (int s = 0; s < NSLICE; s++) {
        esplit<<<ESL * 64 / 256, 256>>>(s * ESL);
        tg<2><<<dim3(4, ESL / 128), blk, SMEM_SZ>>>(eh, el, w2h, w2l, eb2, nullptr, nullptr, s * ESL);
        ln_sum_k<<<NSL / 8, 256>>>(eg, ebt, s * NSL);
    }

    tg<3><<<dim3(4, NN / 128), blk, SMEM_SZ>>>(sh,  sl,  w3h, w3l, eb3, nullptr, nullptr, 0);
    tg<4><<<dim3(4, NN / 128), blk, SMEM_SZ>>>(a4h, a4l, w4h, w4l, nb1, action, nw1, 0);
    tg<5><<<dim3(4, NN / 128), blk, SMEM_SZ>>>(n1h, n1l, w5h, w5l, nb2, nullptr, nullptr, 0);
    ln2_k<<<NN / 8, 256>>>(ng, nbt);
    n3_k<<<NN / 8, 256>>>(nw3, nb3, out);
}